// round 8
// baseline (speedup 1.0000x reference)
#include <cuda_runtime.h>
#include <cuda_bf16.h>
#include <cstdint>

#define NH   8
#define FD   128
#define DVD  16
#define LL   50
#define NT   512

// ---------------- smem layout (bytes) ----------------
#define OFF_SP   0                      // p[2][64] f32
#define OFF_SR   512                    // r[2][64] f32
#define OFF_XHI  1024                   // X hi [128][256B] swizzled bf16
#define OFF_XLO  (OFF_XHI + 32768)
#define OFF_BHI  (OFF_XLO + 32768)      // At hi, then Y hi
#define OFF_BLO  (OFF_BHI + 32768)      // At lo, then Y lo
#define OFF_WHI  (OFF_BLO + 32768)      // Wvt hi [16][256B]
#define OFF_WLO  (OFF_WHI + 4096)
#define OFF_V    (OFF_WLO + 4096)       // V f32 [2][64][16]
#define OFF_P    (OFF_V + 8192)         // P f32 [2][64][65]
#define OFF_SCR  (OFF_P + 2*64*65*4)    // GEMM2 k-split partials [128][66] f32
#define SMEM_TOTAL (OFF_SCR + 128*66*4) // 215552

// ------------- precomputed folded weights -------------
__device__ __align__(16) __nv_bfloat16 g_Ahi[NH][128 * 128];
__device__ __align__(16) __nv_bfloat16 g_Alo[NH][128 * 128];
__device__ __align__(16) __nv_bfloat16 g_Whi[NH][16 * 128];
__device__ __align__(16) __nv_bfloat16 g_Wlo[NH][16 * 128];
__device__ float g_u[NH][FD];
__device__ float g_w[NH][FD];
__device__ float g_c[NH];

// swizzled byte offset in a [rows][128 bf16] tile (256B rows, 16B-chunk XOR)
__host__ __device__ __forceinline__ uint32_t xoff(int r, int c) {
    return (uint32_t)r * 256u
         + (uint32_t)(((((c >> 3) ^ (r & 7))) << 4) + (c & 7) * 2);
}

// ---------------- PTX helpers ----------------
__device__ __forceinline__ uint32_t smem_u32(const void* p) {
    uint32_t a;
    asm("{ .reg .u64 t; cvta.to.shared.u64 t, %1; cvt.u32.u64 %0, t; }"
        : "=r"(a) : "l"(p));
    return a;
}
__device__ __forceinline__ void ldsm_x4(uint32_t a[4], uint32_t addr) {
    asm volatile("ldmatrix.sync.aligned.m8n8.x4.shared.b16 {%0,%1,%2,%3}, [%4];"
                 : "=r"(a[0]), "=r"(a[1]), "=r"(a[2]), "=r"(a[3]) : "r"(addr));
}
__device__ __forceinline__ void ldsm_x2(uint32_t a[2], uint32_t addr) {
    asm volatile("ldmatrix.sync.aligned.m8n8.x2.shared.b16 {%0,%1}, [%2];"
                 : "=r"(a[0]), "=r"(a[1]) : "r"(addr));
}
__device__ __forceinline__ void mma16816(float c[4], const uint32_t a[4],
                                         const uint32_t b[2]) {
    asm volatile(
        "mma.sync.aligned.m16n8k16.row.col.f32.bf16.bf16.f32 "
        "{%0,%1,%2,%3}, {%4,%5,%6,%7}, {%8,%9}, {%0,%1,%2,%3};"
        : "+f"(c[0]), "+f"(c[1]), "+f"(c[2]), "+f"(c[3])
        : "r"(a[0]), "r"(a[1]), "r"(a[2]), "r"(a[3]), "r"(b[0]), "r"(b[1]));
}
#define CP_ASYNC16(s, g) \
    asm volatile("cp.async.cg.shared.global [%0], [%1], 16;" :: "r"(s), "l"(g))
#define CP_COMMIT() asm volatile("cp.async.commit_group;" ::: "memory")
#define CP_WAIT0()  asm volatile("cp.async.wait_group 0;" ::: "memory")

__device__ __forceinline__ uint32_t pack_bf16(float v0, float v1) {
    __nv_bfloat162 t = __floats2bfloat162_rn(v0, v1);
    return *(uint32_t*)&t;
}

// ---------------------------------------------------------------------------
// Kernel 1: fold A = Wq Wk^T (bf16 hi/lo, swizzled At), Wvt hi/lo, biases
// ---------------------------------------------------------------------------
__global__ void precompute_kernel(const float* __restrict__ Wq,
                                  const float* __restrict__ bq,
                                  const float* __restrict__ Wk,
                                  const float* __restrict__ bk,
                                  const float* __restrict__ Wv) {
    const int h     = blockIdx.x;
    const int slice = blockIdx.y;
    const int tid   = threadIdx.x;
    const float* wq = Wq + h * FD * 128;
    const float* wk = Wk + h * FD * 128;

    #pragma unroll
    for (int r = 0; r < 8; r++) {
        int o  = slice * 2048 + r * 256 + tid;
        int f  = o >> 7;
        int fp = o & 127;
        const float* qrow = wq + f * 128;
        const float* krow = wk + fp * 128;
        float acc = 0.f;
        #pragma unroll 8
        for (int e = 0; e < 128; e++) acc += qrow[e] * krow[e];
        __nv_bfloat16 hi = __float2bfloat16(acc);
        float rem = acc - __bfloat162float(hi);
        uint32_t off = xoff(fp, f);
        *(__nv_bfloat16*)((char*)g_Ahi[h] + off) = hi;
        *(__nv_bfloat16*)((char*)g_Alo[h] + off) = __float2bfloat16(rem);
    }
    if (slice == 0) {
        #pragma unroll
        for (int it = 0; it < 8; it++) {
            int idx = it * 256 + tid;
            int dv = idx >> 7, f = idx & 127;
            float v = Wv[h * FD * DVD + f * DVD + dv];
            __nv_bfloat16 hi = __float2bfloat16(v);
            float rem = v - __bfloat162float(hi);
            uint32_t off = xoff(dv, f);
            *(__nv_bfloat16*)((char*)g_Whi[h] + off) = hi;
            *(__nv_bfloat16*)((char*)g_Wlo[h] + off) = __float2bfloat16(rem);
        }
        if (tid < FD) {
            float au = 0.f, aw = 0.f;
            #pragma unroll 8
            for (int e = 0; e < 128; e++) {
                au += wq[tid * 128 + e] * bk[h * 128 + e];
                aw += wk[tid * 128 + e] * bq[h * 128 + e];
            }
            g_u[h][tid] = au;
            g_w[h][tid] = aw;
        }
        if (tid == 128) {
            float c = 0.f;
            for (int e = 0; e < 128; e++) c += bq[h * 128 + e] * bk[h * 128 + e];
            g_c[h] = c;
        }
    }
}

// ---------------------------------------------------------------------------
// Kernel 2: HMMA attention, 512 threads, 2 batches per CTA (M = 128 rows).
// ---------------------------------------------------------------------------
__global__ void __launch_bounds__(NT, 1)
attn_mma_kernel(const float* __restrict__ hid,
                const float* __restrict__ bv,
                float* __restrict__ out) {
    extern __shared__ char smc[];
    const uint32_t sb = smem_u32(smc);
    const int tid  = threadIdx.x;
    const int wid  = tid >> 5;
    const int lane = tid & 31;
    const int bid  = blockIdx.x;

    float* spf  = (float*)(smc + OFF_SP);
    float* srf  = (float*)(smc + OFF_SR);
    float* sVf  = (float*)(smc + OFF_V);
    float* sPf  = (float*)(smc + OFF_P);
    float* scrf = (float*)(smc + OFF_SCR);

    // ---- load x (2 batches), bf16 hi/lo split, swizzled ----
    for (int i = tid; i < 128 * 64; i += NT) {
        int row = i >> 6;
        int cp  = (i & 63) * 2;
        int bb = row >> 6, l = row & 63;
        float v0 = 0.f, v1 = 0.f;
        if (l < LL) {
            const float* xr = hid + (long long)(2 * bid + bb) * (LL * FD) + l * FD + cp;
            v0 = xr[0]; v1 = xr[1];
        }
        __nv_bfloat16 h0 = __float2bfloat16(v0), h1 = __float2bfloat16(v1);
        float r0 = v0 - __bfloat162float(h0), r1 = v1 - __bfloat162float(h1);
        uint32_t off = xoff(row, cp);
        *(uint32_t*)(smc + OFF_XHI + off) =
            ((uint32_t)__bfloat16_as_ushort(h1) << 16) | __bfloat16_as_ushort(h0);
        *(uint32_t*)(smc + OFF_XLO + off) = pack_bf16(r0, r1);
    }

    // ---- prologue: prefetch head 0 weights ----
    {
        const char* gh = (const char*)g_Ahi[0];
        const char* gl = (const char*)g_Alo[0];
        #pragma unroll
        for (int j = 0; j < 4; j++) {
            uint32_t o = (uint32_t)(j * 8192 + tid * 16);
            CP_ASYNC16(sb + OFF_BHI + o, gh + o);
            CP_ASYNC16(sb + OFF_BLO + o, gl + o);
        }
        if (tid < 256)
            CP_ASYNC16(sb + OFF_WHI + tid * 16, (const char*)g_Whi[0] + tid * 16);
        else
            CP_ASYNC16(sb + OFF_WLO + (tid - 256) * 16,
                       (const char*)g_Wlo[0] + (tid - 256) * 16);
        CP_COMMIT();
    }
    __syncthreads();

    // ---- ldmatrix lane-address components ----
    const int lr   = lane & 7;
    const int quad = lane >> 3;
    const int ahalf = quad >> 1;
    const int i15  = lane & 15;
    const int blr  = i15 & 7;
    const int bhalf = i15 >> 3;
    const uint32_t bRowOff = (uint32_t)blr * 256u;
    const int g  = lane >> 2;
    const int tg = lane & 3;

    // GEMM1 tiling: 4 m-slices (m32) x 4 n-quarters (4 Y tiles; V rider nq<2)
    const int ms = wid & 3;
    const int nq = wid >> 2;
    const uint32_t aRow1 = (uint32_t)(ms * 32 + lr + ((quad & 1) << 3)) * 256u;
    // GEMM2 tiling: batch | m-slice(16) | k-half per warp
    const int bbg = wid >> 3;
    const int msl = (wid >> 1) & 3;
    const int kh  = wid & 1;
    const uint32_t aRow2 =
        (uint32_t)(bbg * 64 + msl * 16 + lr + ((quad & 1) << 3)) * 256u;

    for (int h = 0; h < NH; h++) {
        // ======== stage A: p/r scalar; wait prefetched At/Wvt ========
        if (tid < 256) {
            int bb = tid >> 7, which = (tid >> 6) & 1, idx = tid & 63;
            float acc = which ? 0.f : g_c[h];
            if (idx < LL) {
                const float* xr = hid + (long long)(2 * bid + bb) * (LL * FD) + idx * FD;
                const float* vec = which ? g_w[h] : g_u[h];
                #pragma unroll 4
                for (int f = 0; f < FD; f += 4) {
                    float4 xq = *(const float4*)(xr + f);
                    acc += xq.x * vec[f] + xq.y * vec[f + 1]
                         + xq.z * vec[f + 2] + xq.w * vec[f + 3];
                }
            }
            (which ? srf : spf)[bb * 64 + idx] = acc;
        }
        CP_WAIT0();
        __syncthreads();

        // ======== stage B: GEMM1  Y = X·Atᵀ + V rider, m32 x n-quarter ====
        float cY[2][4][4];
        float cV[2][4];
        #pragma unroll
        for (int mt = 0; mt < 2; mt++) {
            #pragma unroll
            for (int n = 0; n < 4; n++)
                #pragma unroll
                for (int q = 0; q < 4; q++) cY[mt][n][q] = 0.f;
            #pragma unroll
            for (int q = 0; q < 4; q++) cV[mt][q] = 0.f;
        }

        #pragma unroll
        for (int k = 0; k < 8; k++) {
            uint32_t ca = (uint32_t)(((2 * k + ahalf) ^ lr) << 4);
            uint32_t ahi0[4], alo0[4], ahi1[4], alo1[4];
            ldsm_x4(ahi0, sb + OFF_XHI + aRow1 + ca);
            ldsm_x4(alo0, sb + OFF_XLO + aRow1 + ca);
            ldsm_x4(ahi1, sb + OFF_XHI + aRow1 + 4096u + ca);
            ldsm_x4(alo1, sb + OFF_XLO + aRow1 + 4096u + ca);
            uint32_t cb = (uint32_t)(((2 * k + bhalf) ^ blr) << 4);
            uint32_t bo = bRowOff + cb;
            #pragma unroll
            for (int j = 0; j < 4; j++) {
                uint32_t o = bo + (uint32_t)((nq * 4 + j) * 2048);
                uint32_t bh[2], bl[2];
                ldsm_x2(bh, sb + OFF_BHI + o);
                ldsm_x2(bl, sb + OFF_BLO + o);
                mma16816(cY[0][j], ahi0, bh);
                mma16816(cY[0][j], ahi0, bl);
                mma16816(cY[0][j], alo0, bh);
                mma16816(cY[1][j], ahi1, bh);
                mma16816(cY[1][j], ahi1, bl);
                mma16816(cY[1][j], alo1, bh);
            }
            if (nq < 2) {
                uint32_t o = bo + (uint32_t)(nq * 2048);
                uint32_t bh[2], bl[2];
                ldsm_x2(bh, sb + OFF_WHI + o);
                ldsm_x2(bl, sb + OFF_WLO + o);
                mma16816(cV[0], ahi0, bh);
                mma16816(cV[0], ahi0, bl);
                mma16816(cV[0], alo0, bh);
                mma16816(cV[1], ahi1, bh);
                mma16816(cV[1], ahi1, bl);
                mma16816(cV[1], alo1, bh);
            }
        }
        __syncthreads();   // all warps done reading At before overwrite

        // ======== stage C: store Y (hi/lo) into B buffers, V into smem ====
        #pragma unroll
        for (int mt = 0; mt < 2; mt++) {
            const int rbase = ms * 32 + mt * 16;
            #pragma unroll
            for (int j = 0; j < 4; j++) {
                int col = (nq * 4 + j) * 8 + tg * 2;
                uint32_t o0 = xoff(rbase + g, col);
                uint32_t o1 = xoff(rbase + 8 + g, col);
                float y0 = cY[mt][j][0], y1 = cY[mt][j][1];
                float y2 = cY[mt][j][2], y3 = cY[mt][j][3];
                __nv_bfloat16 h0 = __float2bfloat16(y0), h1 = __float2bfloat16(y1);
                __nv_bfloat16 h2 = __float2bfloat16(y2), h3 = __float2bfloat16(y3);
                *(uint32_t*)(smc + OFF_BHI + o0) =
                    ((uint32_t)__bfloat16_as_ushort(h1) << 16) | __bfloat16_as_ushort(h0);
                *(uint32_t*)(smc + OFF_BHI + o1) =
                    ((uint32_t)__bfloat16_as_ushort(h3) << 16) | __bfloat16_as_ushort(h2);
                *(uint32_t*)(smc + OFF_BLO + o0) =
                    pack_bf16(y0 - __bfloat162float(h0), y1 - __bfloat162float(h1));
                *(uint32_t*)(smc + OFF_BLO + o1) =
                    pack_bf16(y2 - __bfloat162float(h2), y3 - __bfloat162float(h3));
            }
            if (nq < 2) {
                const int dv = nq * 8 + tg * 2;
                const int bb = rbase >> 6, ml = (rbase & 63) + g;
                float b0 = bv[h * DVD + dv], b1 = bv[h * DVD + dv + 1];
                float* v0 = sVf + (bb * 64 + ml) * 16 + dv;
                float* v1 = sVf + (bb * 64 + ml + 8) * 16 + dv;
                v0[0] = cV[mt][0] + b0;  v0[1] = cV[mt][1] + b1;
                v1[0] = cV[mt][2] + b0;  v1[1] = cV[mt][3] + b1;
            }
        }
        __syncthreads();

        // ======== stage D: GEMM2  C2[m,l] = X·Yᵀ, k split across warp pair ==
        float cS[8][4];
        #pragma unroll
        for (int n = 0; n < 8; n++)
            #pragma unroll
            for (int q = 0; q < 4; q++) cS[n][q] = 0.f;
        const uint32_t ybase = (uint32_t)(bbg * 64 * 256);
        #pragma unroll
        for (int kk = 0; kk < 4; kk++) {
            const int k = kh * 4 + kk;
            uint32_t ca = (uint32_t)(((2 * k + ahalf) ^ lr) << 4);
            uint32_t ahi[4], alo[4];
            ldsm_x4(ahi, sb + OFF_XHI + aRow2 + ca);
            ldsm_x4(alo, sb + OFF_XLO + aRow2 + ca);
            uint32_t cb = (uint32_t)(((2 * k + bhalf) ^ blr) << 4);
            uint32_t bo = ybase + bRowOff + cb;
            #pragma unroll
            for (int n = 0; n < 8; n++) {
                uint32_t o = bo + (uint32_t)(n * 2048);
                uint32_t bh[2], bl[2];
                ldsm_x2(bh, sb + OFF_BHI + o);
                ldsm_x2(bl, sb + OFF_BLO + o);
                mma16816(cS[n], ahi, bh);
                mma16816(cS[n], ahi, bl);
                mma16816(cS[n], alo, bh);
            }
        }
        // k-half 1 publishes partials
        if (kh == 1) {
            float* s0 = scrf + (bbg * 64 + msl * 16 + g) * 66 + tg * 2;
            float* s1 = s0 + 8 * 66;
            #pragma unroll
            for (int n = 0; n < 8; n++) {
                *(float2*)(s0 + n * 8) = make_float2(cS[n][0], cS[n][1]);
                *(float2*)(s1 + n * 8) = make_float2(cS[n][2], cS[n][3]);
            }
        }
        __syncthreads();   // Y reads + partials done before B overwrite

        // ======== prefetch next head's At/Wvt into dead B buffers ========
        if (h + 1 < NH) {
            const char* gh = (const char*)g_Ahi[h + 1];
            const char* gl = (const char*)g_Alo[h + 1];
            #pragma unroll
            for (int j = 0; j < 4; j++) {
                uint32_t o = (uint32_t)(j * 8192 + tid * 16);
                CP_ASYNC16(sb + OFF_BHI + o, gh + o);
                CP_ASYNC16(sb + OFF_BLO + o, gl + o);
            }
            if (tid < 256)
                CP_ASYNC16(sb + OFF_WHI + tid * 16,
                           (const char*)g_Whi[h + 1] + tid * 16);
            else
                CP_ASYNC16(sb + OFF_WLO + (tid - 256) * 16,
                           (const char*)g_Wlo[h + 1] + (tid - 256) * 16);
            CP_COMMIT();
        }

        // ======== stage E: add partials + bias + leaky + softmax (kh==0) ====
        if (kh == 0) {
            #pragma unroll
            for (int pair = 0; pair < 2; pair++) {
                const int mloc = msl * 16 + pair * 8 + g;
                const float rm = srf[bbg * 64 + mloc];
                const float* prt = scrf + (bbg * 64 + mloc) * 66 + tg * 2;
                float vals[16];
                float mx = -1e30f;
                #pragma unroll
                for (int n = 0; n < 8; n++) {
                    float2 pp = *(const float2*)(prt + n * 8);
                    int l0 = n * 8 + tg * 2;
                    float v0 = cS[n][pair * 2]     + pp.x + spf[bbg * 64 + l0]     + rm;
                    float v1 = cS[n][pair * 2 + 1] + pp.y + spf[bbg * 64 + l0 + 1] + rm;
                    v0 = v0 > 0.f ? v0 : 0.1f * v0;
                    v1 = v1 > 0.f ? v1 : 0.1f * v1;
                    if (l0 >= LL)     v0 = -1e30f;
                    if (l0 + 1 >= LL) v1 = -1e30f;
                    vals[n * 2]     = v0;
                    vals[n * 2 + 1] = v1;
                    mx = fmaxf(mx, fmaxf(v0, v1));
                }
                mx = fmaxf(mx, __shfl_xor_sync(0xffffffffu, mx, 1));
                mx = fmaxf(mx, __shfl_xor_sync(0xffffffffu, mx, 2));
                float sum = 0.f;
                #pragma unroll
                for (int q = 0; q < 16; q++) {
                    float e = __expf(vals[q] - mx);
                    vals[q] = e;
                    sum += e;
                }
                sum += __shfl_xor_sync(0xffffffffu, sum, 1);
                sum += __shfl_xor_sync(0xffffffffu, sum, 2);
                float inv = 1.f / sum;
                float* prow = sPf + (bbg * 64 + mloc) * 65;
                #pragma unroll
                for (int n = 0; n < 8; n++) {
                    prow[n * 8 + tg * 2]     = vals[n * 2] * inv;
                    prow[n * 8 + tg * 2 + 1] = vals[n * 2 + 1] * inv;
                }
            }
        }
        __syncthreads();

        // ======== stage F: out = relu(Pᵀ·V), store head slice ========
        {
            int b2 = tid >> 8, l = (tid >> 2) & 63, dv = (tid & 3) * 4;
            if (l < LL) {
                float4 acc = make_float4(0.f, 0.f, 0.f, 0.f);
                const float* pcol = sPf + b2 * 64 * 65 + l;
                const float* vb   = sVf + b2 * 1024 + dv;
                #pragma unroll 10
                for (int m = 0; m < LL; m++) {
                    float p = pcol[m * 65];
                    float4 vv = *(const float4*)(vb + m * 16);
                    acc.x += p * vv.x;  acc.y += p * vv.y;
                    acc.z += p * vv.z;  acc.w += p * vv.w;
                }
                acc.x = fmaxf(acc.x, 0.f);  acc.y = fmaxf(acc.y, 0.f);
                acc.z = fmaxf(acc.z, 0.f);  acc.w = fmaxf(acc.w, 0.f);
                *(float4*)(out + (long long)(2 * bid + b2) * (LL * NH * DVD)
                               + l * (NH * DVD) + h * DVD + dv) = acc;
            }
        }
    }
}

// ---------------------------------------------------------------------------
extern "C" void kernel_launch(void* const* d_in, const int* in_sizes, int n_in,
                              void* d_out, int out_size) {
    const float* hid = (const float*)d_in[0];
    const float* Wq  = (const float*)d_in[1];
    const float* bq  = (const float*)d_in[2];
    const float* Wk  = (const float*)d_in[3];
    const float* bk  = (const float*)d_in[4];
    const float* Wv  = (const float*)d_in[5];
    const float* bv  = (const float*)d_in[6];
    float* out = (float*)d_out;

    const int nb = in_sizes[0] / (LL * FD);

    cudaFuncSetAttribute(attn_mma_kernel,
                         cudaFuncAttributeMaxDynamicSharedMemorySize, SMEM_TOTAL);

    precompute_kernel<<<dim3(NH, 8), 256>>>(Wq, bq, Wk, bk, Wv);
    attn_mma_kernel<<<nb / 2, NT, SMEM_TOTAL>>>(hid, bv, out);
}

// round 9
// speedup vs baseline: 1.1682x; 1.1682x over previous
#include <cuda_runtime.h>
#include <cuda_bf16.h>
#include <cstdint>

#define NH   8
#define FD   128
#define DVD  16
#define LL   50
#define NT   256

// ---------------- smem layout (bytes) ----------------
#define OFF_SP   0                      // p[2][64] f32
#define OFF_SR   512                    // r[2][64] f32
#define OFF_XHI  1024                   // X hi [128][256B] swizzled bf16
#define OFF_XLO  (OFF_XHI + 32768)
#define OFF_AHI  (OFF_XLO + 32768)      // At hi (persistent per head)
#define OFF_ALO  (OFF_AHI + 32768)      // At lo
#define OFF_WHI  (OFF_ALO + 32768)      // Wvt hi [16][256B]
#define OFF_WLO  (OFF_WHI + 4096)
#define OFF_YHI  (OFF_WLO + 4096)       // Y hi [128][256B] swizzled
#define OFF_V    (OFF_YHI + 32768)      // V f32 [2][64][16]
#define OFF_P    (OFF_V + 8192)         // Ylo (GEMM phase) / P f32 [2][64][65]
#define SMEM_TOTAL (OFF_P + 2*64*65*4)  // 214528

// ------------- precomputed folded weights -------------
__device__ __align__(16) __nv_bfloat16 g_Ahi[NH][128 * 128];
__device__ __align__(16) __nv_bfloat16 g_Alo[NH][128 * 128];
__device__ __align__(16) __nv_bfloat16 g_Whi[NH][16 * 128];
__device__ __align__(16) __nv_bfloat16 g_Wlo[NH][16 * 128];
__device__ float g_u[NH][FD];
__device__ float g_w[NH][FD];
__device__ float g_c[NH];

// swizzled byte offset in a [rows][128 bf16] tile (256B rows, 16B-chunk XOR)
__host__ __device__ __forceinline__ uint32_t xoff(int r, int c) {
    return (uint32_t)r * 256u
         + (uint32_t)(((((c >> 3) ^ (r & 7))) << 4) + (c & 7) * 2);
}

// ---------------- PTX helpers ----------------
__device__ __forceinline__ uint32_t smem_u32(const void* p) {
    uint32_t a;
    asm("{ .reg .u64 t; cvta.to.shared.u64 t, %1; cvt.u32.u64 %0, t; }"
        : "=r"(a) : "l"(p));
    return a;
}
__device__ __forceinline__ void ldsm_x4(uint32_t a[4], uint32_t addr) {
    asm volatile("ldmatrix.sync.aligned.m8n8.x4.shared.b16 {%0,%1,%2,%3}, [%4];"
                 : "=r"(a[0]), "=r"(a[1]), "=r"(a[2]), "=r"(a[3]) : "r"(addr));
}
__device__ __forceinline__ void ldsm_x2(uint32_t a[2], uint32_t addr) {
    asm volatile("ldmatrix.sync.aligned.m8n8.x2.shared.b16 {%0,%1}, [%2];"
                 : "=r"(a[0]), "=r"(a[1]) : "r"(addr));
}
__device__ __forceinline__ void mma16816(float c[4], const uint32_t a[4],
                                         const uint32_t b[2]) {
    asm volatile(
        "mma.sync.aligned.m16n8k16.row.col.f32.bf16.bf16.f32 "
        "{%0,%1,%2,%3}, {%4,%5,%6,%7}, {%8,%9}, {%0,%1,%2,%3};"
        : "+f"(c[0]), "+f"(c[1]), "+f"(c[2]), "+f"(c[3])
        : "r"(a[0]), "r"(a[1]), "r"(a[2]), "r"(a[3]), "r"(b[0]), "r"(b[1]));
}
#define CP_ASYNC16(s, g) \
    asm volatile("cp.async.cg.shared.global [%0], [%1], 16;" :: "r"(s), "l"(g))
#define CP_COMMIT() asm volatile("cp.async.commit_group;" ::: "memory")
#define CP_WAIT0()  asm volatile("cp.async.wait_group 0;" ::: "memory")

__device__ __forceinline__ uint32_t pack_bf16(float v0, float v1) {
    __nv_bfloat162 t = __floats2bfloat162_rn(v0, v1);
    return *(uint32_t*)&t;
}

// ---------------------------------------------------------------------------
// Kernel 1: fold A = Wq Wk^T (bf16 hi/lo, swizzled At), Wvt hi/lo, biases
// ---------------------------------------------------------------------------
__global__ void precompute_kernel(const float* __restrict__ Wq,
                                  const float* __restrict__ bq,
                                  const float* __restrict__ Wk,
                                  const float* __restrict__ bk,
                                  const float* __restrict__ Wv) {
    const int h     = blockIdx.x;
    const int slice = blockIdx.y;
    const int tid   = threadIdx.x;
    const float* wq = Wq + h * FD * 128;
    const float* wk = Wk + h * FD * 128;

    #pragma unroll
    for (int r = 0; r < 8; r++) {
        int o  = slice * 2048 + r * 256 + tid;
        int f  = o >> 7;
        int fp = o & 127;
        const float* qrow = wq + f * 128;
        const float* krow = wk + fp * 128;
        float acc = 0.f;
        #pragma unroll 8
        for (int e = 0; e < 128; e++) acc += qrow[e] * krow[e];
        __nv_bfloat16 hi = __float2bfloat16(acc);
        float rem = acc - __bfloat162float(hi);
        uint32_t off = xoff(fp, f);
        *(__nv_bfloat16*)((char*)g_Ahi[h] + off) = hi;
        *(__nv_bfloat16*)((char*)g_Alo[h] + off) = __float2bfloat16(rem);
    }
    if (slice == 0) {
        #pragma unroll
        for (int it = 0; it < 8; it++) {
            int idx = it * 256 + tid;
            int dv = idx >> 7, f = idx & 127;
            float v = Wv[h * FD * DVD + f * DVD + dv];
            __nv_bfloat16 hi = __float2bfloat16(v);
            float rem = v - __bfloat162float(hi);
            uint32_t off = xoff(dv, f);
            *(__nv_bfloat16*)((char*)g_Whi[h] + off) = hi;
            *(__nv_bfloat16*)((char*)g_Wlo[h] + off) = __float2bfloat16(rem);
        }
        if (tid < FD) {
            float au = 0.f, aw = 0.f;
            #pragma unroll 8
            for (int e = 0; e < 128; e++) {
                au += wq[tid * 128 + e] * bk[h * 128 + e];
                aw += wk[tid * 128 + e] * bq[h * 128 + e];
            }
            g_u[h][tid] = au;
            g_w[h][tid] = aw;
        }
        if (tid == 128) {
            float c = 0.f;
            for (int e = 0; e < 128; e++) c += bq[h * 128 + e] * bk[h * 128 + e];
            g_c[h] = c;
        }
    }
}

// ---------------------------------------------------------------------------
// Kernel 2: HMMA attention, 256 threads, 2 batches per CTA (M = 128 rows).
// Barrier schedule: s1 (inputs ready) -> GEMM1+Ywb -> s2 -> prefetch+GEMM2
// -> s3 -> softmax -> s4 -> PV.
// ---------------------------------------------------------------------------
__global__ void __launch_bounds__(NT, 1)
attn_mma_kernel(const float* __restrict__ hid,
                const float* __restrict__ bv,
                float* __restrict__ out) {
    extern __shared__ char smc[];
    const uint32_t sb = smem_u32(smc);
    const int tid  = threadIdx.x;
    const int wid  = tid >> 5;
    const int lane = tid & 31;
    const int bid  = blockIdx.x;

    float* spf = (float*)(smc + OFF_SP);
    float* srf = (float*)(smc + OFF_SR);
    float* sVf = (float*)(smc + OFF_V);
    float* sPf = (float*)(smc + OFF_P);

    // ---- load x (2 batches), bf16 hi/lo split, swizzled ----
    for (int i = tid; i < 128 * 64; i += NT) {
        int row = i >> 6;
        int cp  = (i & 63) * 2;
        int bb = row >> 6, l = row & 63;
        float v0 = 0.f, v1 = 0.f;
        if (l < LL) {
            const float* xr = hid + (long long)(2 * bid + bb) * (LL * FD) + l * FD + cp;
            v0 = xr[0]; v1 = xr[1];
        }
        __nv_bfloat16 h0 = __float2bfloat16(v0), h1 = __float2bfloat16(v1);
        float r0 = v0 - __bfloat162float(h0), r1 = v1 - __bfloat162float(h1);
        uint32_t off = xoff(row, cp);
        *(uint32_t*)(smc + OFF_XHI + off) =
            ((uint32_t)__bfloat16_as_ushort(h1) << 16) | __bfloat16_as_ushort(h0);
        *(uint32_t*)(smc + OFF_XLO + off) = pack_bf16(r0, r1);
    }

    // ---- prologue: prefetch head 0 weights ----
    {
        const char* gh = (const char*)g_Ahi[0];
        const char* gl = (const char*)g_Alo[0];
        #pragma unroll
        for (int j = 0; j < 8; j++) {
            uint32_t o = (uint32_t)(j * 4096 + tid * 16);
            CP_ASYNC16(sb + OFF_AHI + o, gh + o);
            CP_ASYNC16(sb + OFF_ALO + o, gl + o);
        }
        CP_ASYNC16(sb + OFF_WHI + tid * 16, (const char*)g_Whi[0] + tid * 16);
        CP_ASYNC16(sb + OFF_WLO + tid * 16, (const char*)g_Wlo[0] + tid * 16);
        CP_COMMIT();
    }

    // ---- ldmatrix lane-address components ----
    const int lr   = lane & 7;
    const int quad = lane >> 3;
    const int ahalf = quad >> 1;
    const int i15  = lane & 15;
    const int blr  = i15 & 7;
    const int bhalf = i15 >> 3;
    const uint32_t bRowOff = (uint32_t)blr * 256u;
    const int g  = lane >> 2;
    const int tg = lane & 3;

    // GEMM1 tiling: 4 m-slices (m32) x 2 n-halves
    const int ms = wid & 3;
    const int nh = wid >> 2;
    const uint32_t aRow1 = (uint32_t)(ms * 32 + lr + ((quad & 1) << 3)) * 256u;
    // GEMM2 tiling: m16 per warp, all n of batch bb2
    const uint32_t aRow2 = (uint32_t)(wid * 16 + lr + ((quad & 1) << 3)) * 256u;
    const int bb2 = wid >> 2;

    for (int h = 0; h < NH; h++) {
        // ======== stage A: p/r scalar; complete pending prefetch ========
        {
            int bb = tid >> 7, which = (tid >> 6) & 1, idx = tid & 63;
            float acc = which ? 0.f : g_c[h];
            if (idx < LL) {
                const float* xr = hid + (long long)(2 * bid + bb) * (LL * FD) + idx * FD;
                const float* vec = which ? g_w[h] : g_u[h];
                #pragma unroll 4
                for (int f = 0; f < FD; f += 4) {
                    float4 xq = *(const float4*)(xr + f);
                    acc += xq.x * vec[f] + xq.y * vec[f + 1]
                         + xq.z * vec[f + 2] + xq.w * vec[f + 3];
                }
            }
            (which ? srf : spf)[bb * 64 + idx] = acc;
        }
        CP_WAIT0();
        __syncthreads();                                   // ---- s1 ----

        // ======== stage B: GEMM1  Y = X·Atᵀ + V rider, m32 x n-half ========
        float cY[2][8][4];
        float cV[2][4];
        #pragma unroll
        for (int mt = 0; mt < 2; mt++) {
            #pragma unroll
            for (int n = 0; n < 8; n++)
                #pragma unroll
                for (int q = 0; q < 4; q++) cY[mt][n][q] = 0.f;
            #pragma unroll
            for (int q = 0; q < 4; q++) cV[mt][q] = 0.f;
        }

        #pragma unroll
        for (int k = 0; k < 8; k++) {
            uint32_t ca = (uint32_t)(((2 * k + ahalf) ^ lr) << 4);
            uint32_t ahi0[4], alo0[4], ahi1[4], alo1[4];
            ldsm_x4(ahi0, sb + OFF_XHI + aRow1 + ca);
            ldsm_x4(alo0, sb + OFF_XLO + aRow1 + ca);
            ldsm_x4(ahi1, sb + OFF_XHI + aRow1 + 4096u + ca);
            ldsm_x4(alo1, sb + OFF_XLO + aRow1 + 4096u + ca);
            uint32_t cb = (uint32_t)(((2 * k + bhalf) ^ blr) << 4);
            uint32_t bo = bRowOff + cb;
            #pragma unroll
            for (int j = 0; j < 8; j++) {
                uint32_t o = bo + (uint32_t)((nh * 8 + j) * 2048);
                uint32_t bh[2], bl[2];
                ldsm_x2(bh, sb + OFF_AHI + o);
                ldsm_x2(bl, sb + OFF_ALO + o);
                mma16816(cY[0][j], ahi0, bh);
                mma16816(cY[0][j], ahi0, bl);
                mma16816(cY[0][j], alo0, bh);
                mma16816(cY[1][j], ahi1, bh);
                mma16816(cY[1][j], ahi1, bl);
                mma16816(cY[1][j], alo1, bh);
            }
            {
                uint32_t o = bo + (uint32_t)(nh * 2048);
                uint32_t bh[2], bl[2];
                ldsm_x2(bh, sb + OFF_WHI + o);
                ldsm_x2(bl, sb + OFF_WLO + o);
                mma16816(cV[0], ahi0, bh);
                mma16816(cV[0], ahi0, bl);
                mma16816(cV[0], alo0, bh);
                mma16816(cV[1], ahi1, bh);
                mma16816(cV[1], ahi1, bl);
                mma16816(cV[1], alo1, bh);
            }
        }

        // ======== stage C: write Y (hi->YHI, lo->P region) and V ========
        // (no barrier needed before this: targets are disjoint from GEMM1 reads)
        #pragma unroll
        for (int mt = 0; mt < 2; mt++) {
            const int rbase = ms * 32 + mt * 16;
            #pragma unroll
            for (int j = 0; j < 8; j++) {
                int col = nh * 64 + j * 8 + tg * 2;
                uint32_t o0 = xoff(rbase + g, col);
                uint32_t o1 = xoff(rbase + 8 + g, col);
                float y0 = cY[mt][j][0], y1 = cY[mt][j][1];
                float y2 = cY[mt][j][2], y3 = cY[mt][j][3];
                __nv_bfloat16 h0 = __float2bfloat16(y0), h1 = __float2bfloat16(y1);
                __nv_bfloat16 h2 = __float2bfloat16(y2), h3 = __float2bfloat16(y3);
                *(uint32_t*)(smc + OFF_YHI + o0) =
                    ((uint32_t)__bfloat16_as_ushort(h1) << 16) | __bfloat16_as_ushort(h0);
                *(uint32_t*)(smc + OFF_YHI + o1) =
                    ((uint32_t)__bfloat16_as_ushort(h3) << 16) | __bfloat16_as_ushort(h2);
                *(uint32_t*)(smc + OFF_P + o0) =
                    pack_bf16(y0 - __bfloat162float(h0), y1 - __bfloat162float(h1));
                *(uint32_t*)(smc + OFF_P + o1) =
                    pack_bf16(y2 - __bfloat162float(h2), y3 - __bfloat162float(h3));
            }
            {
                const int dv = nh * 8 + tg * 2;
                const int bb = rbase >> 6, ml = (rbase & 63) + g;
                float b0 = bv[h * DVD + dv], b1 = bv[h * DVD + dv + 1];
                float* v0 = sVf + (bb * 64 + ml) * 16 + dv;
                float* v1 = sVf + (bb * 64 + ml + 8) * 16 + dv;
                v0[0] = cV[mt][0] + b0;  v0[1] = cV[mt][1] + b1;
                v1[0] = cV[mt][2] + b0;  v1[1] = cV[mt][3] + b1;
            }
        }
        __syncthreads();                                   // ---- s2 ----

        // ======== prefetch next head's At/Wvt (overlaps GEMM2/E/F) ========
        if (h + 1 < NH) {
            const char* gh = (const char*)g_Ahi[h + 1];
            const char* gl = (const char*)g_Alo[h + 1];
            #pragma unroll
            for (int j = 0; j < 8; j++) {
                uint32_t o = (uint32_t)(j * 4096 + tid * 16);
                CP_ASYNC16(sb + OFF_AHI + o, gh + o);
                CP_ASYNC16(sb + OFF_ALO + o, gl + o);
            }
            CP_ASYNC16(sb + OFF_WHI + tid * 16, (const char*)g_Whi[h + 1] + tid * 16);
            CP_ASYNC16(sb + OFF_WLO + tid * 16, (const char*)g_Wlo[h + 1] + tid * 16);
            CP_COMMIT();
        }

        // ======== stage D: GEMM2  C2[m,l] = X·Yᵀ (m16, all n of batch) ====
        float cS[8][4];
        #pragma unroll
        for (int n = 0; n < 8; n++)
            #pragma unroll
            for (int q = 0; q < 4; q++) cS[n][q] = 0.f;
        const uint32_t ybase = (uint32_t)(bb2 * 64 * 256);
        #pragma unroll
        for (int k = 0; k < 8; k++) {
            uint32_t ca = (uint32_t)(((2 * k + ahalf) ^ lr) << 4);
            uint32_t ahi[4], alo[4];
            ldsm_x4(ahi, sb + OFF_XHI + aRow2 + ca);
            ldsm_x4(alo, sb + OFF_XLO + aRow2 + ca);
            uint32_t cb = (uint32_t)(((2 * k + bhalf) ^ blr) << 4);
            uint32_t bo = ybase + bRowOff + cb;
            #pragma unroll
            for (int n = 0; n < 8; n++) {
                uint32_t o = bo + (uint32_t)(n * 2048);
                uint32_t bh[2], bl[2];
                ldsm_x2(bh, sb + OFF_YHI + o);
                ldsm_x2(bl, sb + OFF_P + o);
                mma16816(cS[n], ahi, bh);
                mma16816(cS[n], ahi, bl);
                mma16816(cS[n], alo, bh);
            }
        }
        __syncthreads();                                   // ---- s3 ----

        // ======== stage E: bias + leaky + softmax over l, P -> smem ========
        {
            const int mbase = ((wid & 3) << 4) + g;
            #pragma unroll
            for (int pair = 0; pair < 2; pair++) {
                const int m = mbase + pair * 8;
                const float rm = srf[bb2 * 64 + m];
                float vals[16];
                float mx = -1e30f;
                #pragma unroll
                for (int n = 0; n < 8; n++) {
                    #pragma unroll
                    for (int j = 0; j < 2; j++) {
                        int l = n * 8 + tg * 2 + j;
                        float v = cS[n][pair * 2 + j] + spf[bb2 * 64 + l] + rm;
                        v = v > 0.f ? v : 0.1f * v;
                        if (l >= LL) v = -1e30f;
                        vals[n * 2 + j] = v;
                        mx = fmaxf(mx, v);
                    }
                }
                mx = fmaxf(mx, __shfl_xor_sync(0xffffffffu, mx, 1));
                mx = fmaxf(mx, __shfl_xor_sync(0xffffffffu, mx, 2));
                float sum = 0.f;
                #pragma unroll
                for (int q = 0; q < 16; q++) {
                    float e = __expf(vals[q] - mx);
                    vals[q] = e;
                    sum += e;
                }
                sum += __shfl_xor_sync(0xffffffffu, sum, 1);
                sum += __shfl_xor_sync(0xffffffffu, sum, 2);
                float inv = 1.f / sum;
                float* prow = sPf + (bb2 * 64 + m) * 65;
                #pragma unroll
                for (int n = 0; n < 8; n++) {
                    prow[n * 8 + tg * 2]     = vals[n * 2] * inv;
                    prow[n * 8 + tg * 2 + 1] = vals[n * 2 + 1] * inv;
                }
            }
        }
        __syncthreads();                                   // ---- s4 ----

        // ======== stage F: out = relu(Pᵀ·V), store head slice ========
        #pragma unroll
        for (int it = 0; it < 2; it++) {
            int item = tid + it * NT;
            int b2 = item >> 8, l = (item >> 2) & 63, dv = (item & 3) * 4;
            if (l < LL) {
                float4 acc = make_float4(0.f, 0.f, 0.f, 0.f);
                const float* pcol = sPf + b2 * 64 * 65 + l;
                const float* vb   = sVf + b2 * 1024 + dv;
                #pragma unroll 10
                for (int m = 0; m < LL; m++) {
                    float p = pcol[m * 65];
                    float4 vv = *(const float4*)(vb + m * 16);
                    acc.x += p * vv.x;  acc.y += p * vv.y;
                    acc.z += p * vv.z;  acc.w += p * vv.w;
                }
                acc.x = fmaxf(acc.x, 0.f);  acc.y = fmaxf(acc.y, 0.f);
                acc.z = fmaxf(acc.z, 0.f);  acc.w = fmaxf(acc.w, 0.f);
                *(float4*)(out + (long long)(2 * bid + b2) * (LL * NH * DVD)
                               + l * (NH * DVD) + h * DVD + dv) = acc;
            }
        }
    }
}

// ---------------------------------------------------------------------------
extern "C" void kernel_launch(void* const* d_in, const int* in_sizes, int n_in,
                              void* d_out, int out_size) {
    const float* hid = (const float*)d_in[0];
    const float* Wq  = (const float*)d_in[1];
    const float* bq  = (const float*)d_in[2];
    const float* Wk  = (const float*)d_in[3];
    const float* bk  = (const float*)d_in[4];
    const float* Wv  = (const float*)d_in[5];
    const float* bv  = (const float*)d_in[6];
    float* out = (float*)d_out;

    const int nb = in_sizes[0] / (LL * FD);

    cudaFuncSetAttribute(attn_mma_kernel,
                         cudaFuncAttributeMaxDynamicSharedMemorySize, SMEM_TOTAL);

    precompute_kernel<<<dim3(NH, 8), 256>>>(Wq, bq, Wk, bk, Wv);
    attn_mma_kernel<<<nb / 2, NT, SMEM_TOTAL>>>(hid, bv, out);
}

// round 10
// speedup vs baseline: 1.2474x; 1.0678x over previous
#include <cuda_runtime.h>
#include <cuda_fp16.h>
#include <cstdint>

#define NH   8
#define FD   128
#define DVD  16
#define LL   50
#define NT   256

// ---------------- smem layout (bytes) ----------------
#define OFF_SP   0                      // p_all [2][64][8] f32 (+c folded)
#define OFF_SR   4096                   // r_all [2][64][8] f32
#define OFF_XHI  8192                   // X hi [128][256B] swizzled fp16
#define OFF_XLO  (OFF_XHI + 32768)
#define OFF_AHI  (OFF_XLO + 32768)      // At hi (per head, prefetched)
#define OFF_ALO  (OFF_AHI + 32768)      // At lo
#define OFF_WHI  (OFF_ALO + 32768)      // Wvt hi [16][256B]
#define OFF_WLO  (OFF_WHI + 4096)
#define OFF_YHI  (OFF_WLO + 4096)       // Y hi [128][256B] swizzled
#define OFF_V    (OFF_YHI + 32768)      // V f32 [2][64][16]
#define OFF_P    (OFF_V + 8192)         // Ylo (GEMM phase) / P f32 [2][64][65]
#define SMEM_TOTAL (OFF_P + 2*64*65*4)  // 221696

// ------------- precomputed folded weights (fp16 hi/lo) -------------
__device__ __align__(16) __half g_Ahi[NH][128 * 128];
__device__ __align__(16) __half g_Alo[NH][128 * 128];
__device__ __align__(16) __half g_Whi[NH][16 * 128];
__device__ __align__(16) __half g_Wlo[NH][16 * 128];
__device__ float g_u[NH][FD];
__device__ float g_w[NH][FD];
__device__ float g_c[NH];

// swizzled byte offset in a [rows][128 f16] tile (256B rows, 16B-chunk XOR)
__host__ __device__ __forceinline__ uint32_t xoff(int r, int c) {
    return (uint32_t)r * 256u
         + (uint32_t)(((((c >> 3) ^ (r & 7))) << 4) + (c & 7) * 2);
}

// ---------------- PTX helpers ----------------
__device__ __forceinline__ uint32_t smem_u32(const void* p) {
    uint32_t a;
    asm("{ .reg .u64 t; cvta.to.shared.u64 t, %1; cvt.u32.u64 %0, t; }"
        : "=r"(a) : "l"(p));
    return a;
}
__device__ __forceinline__ void ldsm_x4(uint32_t a[4], uint32_t addr) {
    asm volatile("ldmatrix.sync.aligned.m8n8.x4.shared.b16 {%0,%1,%2,%3}, [%4];"
                 : "=r"(a[0]), "=r"(a[1]), "=r"(a[2]), "=r"(a[3]) : "r"(addr));
}
__device__ __forceinline__ void ldsm_x2(uint32_t a[2], uint32_t addr) {
    asm volatile("ldmatrix.sync.aligned.m8n8.x2.shared.b16 {%0,%1}, [%2];"
                 : "=r"(a[0]), "=r"(a[1]) : "r"(addr));
}
// main term: f16 x f16 -> f32 accum
__device__ __forceinline__ void mma_f32(float c[4], const uint32_t a[4],
                                        const uint32_t b[2]) {
    asm volatile(
        "mma.sync.aligned.m16n8k16.row.col.f32.f16.f16.f32 "
        "{%0,%1,%2,%3}, {%4,%5,%6,%7}, {%8,%9}, {%0,%1,%2,%3};"
        : "+f"(c[0]), "+f"(c[1]), "+f"(c[2]), "+f"(c[3])
        : "r"(a[0]), "r"(a[1]), "r"(a[2]), "r"(a[3]), "r"(b[0]), "r"(b[1]));
}
// correction terms: f16 x f16 -> f16 accum (2x rate path)
__device__ __forceinline__ void mma_f16(uint32_t& d0, uint32_t& d1,
                                        const uint32_t a[4], const uint32_t b[2]) {
    asm volatile(
        "mma.sync.aligned.m16n8k16.row.col.f16.f16.f16.f16 "
        "{%0,%1}, {%2,%3,%4,%5}, {%6,%7}, {%0,%1};"
        : "+r"(d0), "+r"(d1)
        : "r"(a[0]), "r"(a[1]), "r"(a[2]), "r"(a[3]), "r"(b[0]), "r"(b[1]));
}
__device__ __forceinline__ void fold_corr(float c[4], uint32_t d0, uint32_t d1) {
    float2 f0 = __half22float2(*(__half2*)&d0);
    float2 f1 = __half22float2(*(__half2*)&d1);
    c[0] += f0.x;  c[1] += f0.y;  c[2] += f1.x;  c[3] += f1.y;
}
#define CP_ASYNC16(s, g) \
    asm volatile("cp.async.cg.shared.global [%0], [%1], 16;" :: "r"(s), "l"(g))
#define CP_COMMIT() asm volatile("cp.async.commit_group;" ::: "memory")
#define CP_WAIT0()  asm volatile("cp.async.wait_group 0;" ::: "memory")

__device__ __forceinline__ uint32_t pack_f16(float a, float b) {
    __half2 t = __floats2half2_rn(a, b);
    return *(uint32_t*)&t;
}

// ---------------------------------------------------------------------------
// Kernel 1: fold A = Wq Wk^T (fp16 hi/lo, swizzled At), Wvt hi/lo, biases
// ---------------------------------------------------------------------------
__global__ void precompute_kernel(const float* __restrict__ Wq,
                                  const float* __restrict__ bq,
                                  const float* __restrict__ Wk,
                                  const float* __restrict__ bk,
                                  const float* __restrict__ Wv) {
    const int h     = blockIdx.x;
    const int slice = blockIdx.y;
    const int tid   = threadIdx.x;
    const float* wq = Wq + h * FD * 128;
    const float* wk = Wk + h * FD * 128;

    #pragma unroll
    for (int r = 0; r < 8; r++) {
        int o  = slice * 2048 + r * 256 + tid;
        int f  = o >> 7;
        int fp = o & 127;
        const float* qrow = wq + f * 128;
        const float* krow = wk + fp * 128;
        float acc = 0.f;
        #pragma unroll 8
        for (int e = 0; e < 128; e++) acc += qrow[e] * krow[e];
        __half hi = __float2half_rn(acc);
        float rem = acc - __half2float(hi);
        uint32_t off = xoff(fp, f);
        *(__half*)((char*)g_Ahi[h] + off) = hi;
        *(__half*)((char*)g_Alo[h] + off) = __float2half_rn(rem);
    }
    if (slice == 0) {
        #pragma unroll
        for (int it = 0; it < 8; it++) {
            int idx = it * 256 + tid;
            int dv = idx >> 7, f = idx & 127;
            float v = Wv[h * FD * DVD + f * DVD + dv];
            __half hi = __float2half_rn(v);
            float rem = v - __half2float(hi);
            uint32_t off = xoff(dv, f);
            *(__half*)((char*)g_Whi[h] + off) = hi;
            *(__half*)((char*)g_Wlo[h] + off) = __float2half_rn(rem);
        }
        if (tid < FD) {
            float au = 0.f, aw = 0.f;
            #pragma unroll 8
            for (int e = 0; e < 128; e++) {
                au += wq[tid * 128 + e] * bk[h * 128 + e];
                aw += wk[tid * 128 + e] * bq[h * 128 + e];
            }
            g_u[h][tid] = au;
            g_w[h][tid] = aw;
        }
        if (tid == 128) {
            float c = 0.f;
            for (int e = 0; e < 128; e++) c += bq[h * 128 + e] * bk[h * 128 + e];
            g_c[h] = c;
        }
    }
}

// ---------------------------------------------------------------------------
// Kernel 2: HMMA attention, 256 threads, 2 batches per CTA (M = 128 rows).
// fp16 hi/lo; main term f32-accum, corrections f16-accum folded to f32.
// ---------------------------------------------------------------------------
__global__ void __launch_bounds__(NT, 1)
attn_mma_kernel(const float* __restrict__ hid,
                const float* __restrict__ bv,
                float* __restrict__ out) {
    extern __shared__ char smc[];
    const uint32_t sb = smem_u32(smc);
    const int tid  = threadIdx.x;
    const int wid  = tid >> 5;
    const int lane = tid & 31;
    const int bid  = blockIdx.x;

    float* spf = (float*)(smc + OFF_SP);   // [2][64][8]
    float* srf = (float*)(smc + OFF_SR);   // [2][64][8]
    float* sVf = (float*)(smc + OFF_V);
    float* sPf = (float*)(smc + OFF_P);

    // ---- load x (2 batches), fp16 hi/lo split, swizzled ----
    for (int i = tid; i < 128 * 64; i += NT) {
        int row = i >> 6;
        int cp  = (i & 63) * 2;
        int bb = row >> 6, l = row & 63;
        float v0 = 0.f, v1 = 0.f;
        if (l < LL) {
            const float* xr = hid + (long long)(2 * bid + bb) * (LL * FD) + l * FD + cp;
            v0 = xr[0]; v1 = xr[1];
        }
        __half h0 = __float2half_rn(v0), h1 = __float2half_rn(v1);
        float r0 = v0 - __half2float(h0), r1 = v1 - __half2float(h1);
        uint32_t off = xoff(row, cp);
        __half2 hw = __halves2half2(h0, h1);
        *(uint32_t*)(smc + OFF_XHI + off) = *(uint32_t*)&hw;
        *(uint32_t*)(smc + OFF_XLO + off) = pack_f16(r0, r1);
    }

    // ---- prologue: prefetch head 0 weights ----
    {
        const char* gh = (const char*)g_Ahi[0];
        const char* gl = (const char*)g_Alo[0];
        #pragma unroll
        for (int j = 0; j < 8; j++) {
            uint32_t o = (uint32_t)(j * 4096 + tid * 16);
            CP_ASYNC16(sb + OFF_AHI + o, gh + o);
            CP_ASYNC16(sb + OFF_ALO + o, gl + o);
        }
        CP_ASYNC16(sb + OFF_WHI + tid * 16, (const char*)g_Whi[0] + tid * 16);
        CP_ASYNC16(sb + OFF_WLO + tid * 16, (const char*)g_Wlo[0] + tid * 16);
        CP_COMMIT();
    }

    // ---- all-head p/r bias dots, once (overlaps prefetch) ----
    {
        int bb = tid >> 7;
        int l  = (tid >> 1) & 63;
        int pr = tid & 1;
        float acc[8];
        #pragma unroll
        for (int h2 = 0; h2 < 8; h2++) acc[h2] = 0.f;
        if (l < LL) {
            const float* xr = hid + (long long)(2 * bid + bb) * (LL * FD) + l * FD;
            const float* vb = pr ? &g_w[0][0] : &g_u[0][0];
            #pragma unroll 2
            for (int f = 0; f < FD; f += 4) {
                float4 xq = *(const float4*)(xr + f);
                #pragma unroll
                for (int h2 = 0; h2 < 8; h2++) {
                    const float* v = vb + h2 * FD + f;
                    acc[h2] += xq.x * v[0] + xq.y * v[1] + xq.z * v[2] + xq.w * v[3];
                }
            }
        }
        float* dst = pr ? srf : spf;
        #pragma unroll
        for (int h2 = 0; h2 < 8; h2++)
            dst[((bb << 6) + l) * 8 + h2] = acc[h2] + (pr ? 0.f : g_c[h2]);
    }

    // ---- ldmatrix lane-address components ----
    const int lr   = lane & 7;
    const int quad = lane >> 3;
    const int ahalf = quad >> 1;
    const int i15  = lane & 15;
    const int blr  = i15 & 7;
    const int bhalf = i15 >> 3;
    const uint32_t bRowOff = (uint32_t)blr * 256u;
    const int g  = lane >> 2;
    const int tg = lane & 3;

    // GEMM1: 4 m-slices (m32) x 2 n-halves
    const int ms = wid & 3;
    const int nh = wid >> 2;
    const uint32_t aRow1 = (uint32_t)(ms * 32 + lr + ((quad & 1) << 3)) * 256u;
    // GEMM2: m16 per warp, all n of batch bb2
    const uint32_t aRow2 = (uint32_t)(wid * 16 + lr + ((quad & 1) << 3)) * 256u;
    const int bb2 = wid >> 2;

    for (int h = 0; h < NH; h++) {
        CP_WAIT0();
        __syncthreads();                                   // ---- s1 ----

        // ======== GEMM1: Y = X·Atᵀ + V rider (main f32 + f16 corr) ========
        float cY[2][8][4];
        float cV[2][4];
        #pragma unroll
        for (int mt = 0; mt < 2; mt++) {
            #pragma unroll
            for (int n = 0; n < 8; n++)
                #pragma unroll
                for (int q = 0; q < 4; q++) cY[mt][n][q] = 0.f;
            #pragma unroll
            for (int q = 0; q < 4; q++) cV[mt][q] = 0.f;
        }

        #pragma unroll
        for (int k = 0; k < 8; k++) {
            uint32_t ca = (uint32_t)(((2 * k + ahalf) ^ lr) << 4);
            uint32_t ahi0[4], alo0[4], ahi1[4], alo1[4];
            ldsm_x4(ahi0, sb + OFF_XHI + aRow1 + ca);
            ldsm_x4(alo0, sb + OFF_XLO + aRow1 + ca);
            ldsm_x4(ahi1, sb + OFF_XHI + aRow1 + 4096u + ca);
            ldsm_x4(alo1, sb + OFF_XLO + aRow1 + 4096u + ca);
            uint32_t cb = (uint32_t)(((2 * k + bhalf) ^ blr) << 4);
            uint32_t bo = bRowOff + cb;
            #pragma unroll
            for (int j = 0; j < 8; j++) {
                uint32_t o = bo + (uint32_t)((nh * 8 + j) * 2048);
                uint32_t bh[2], bl[2];
                ldsm_x2(bh, sb + OFF_AHI + o);
                ldsm_x2(bl, sb + OFF_ALO + o);
                mma_f32(cY[0][j], ahi0, bh);
                {
                    uint32_t d0 = 0, d1 = 0;
                    mma_f16(d0, d1, ahi0, bl);
                    mma_f16(d0, d1, alo0, bh);
                    fold_corr(cY[0][j], d0, d1);
                }
                mma_f32(cY[1][j], ahi1, bh);
                {
                    uint32_t d0 = 0, d1 = 0;
                    mma_f16(d0, d1, ahi1, bl);
                    mma_f16(d0, d1, alo1, bh);
                    fold_corr(cY[1][j], d0, d1);
                }
            }
            {
                uint32_t o = bo + (uint32_t)(nh * 2048);
                uint32_t bh[2], bl[2];
                ldsm_x2(bh, sb + OFF_WHI + o);
                ldsm_x2(bl, sb + OFF_WLO + o);
                mma_f32(cV[0], ahi0, bh);
                {
                    uint32_t d0 = 0, d1 = 0;
                    mma_f16(d0, d1, ahi0, bl);
                    mma_f16(d0, d1, alo0, bh);
                    fold_corr(cV[0], d0, d1);
                }
                mma_f32(cV[1], ahi1, bh);
                {
                    uint32_t d0 = 0, d1 = 0;
                    mma_f16(d0, d1, ahi1, bl);
                    mma_f16(d0, d1, alo1, bh);
                    fold_corr(cV[1], d0, d1);
                }
            }
        }

        // ======== write Y (hi->YHI, lo->P region) and V ========
        #pragma unroll
        for (int mt = 0; mt < 2; mt++) {
            const int rbase = ms * 32 + mt * 16;
            #pragma unroll
            for (int j = 0; j < 8; j++) {
                int col = nh * 64 + j * 8 + tg * 2;
                uint32_t o0 = xoff(rbase + g, col);
                uint32_t o1 = xoff(rbase + 8 + g, col);
                float y0 = cY[mt][j][0], y1 = cY[mt][j][1];
                float y2 = cY[mt][j][2], y3 = cY[mt][j][3];
                __half h0 = __float2half_rn(y0), h1 = __float2half_rn(y1);
                __half h2 = __float2half_rn(y2), h3 = __float2half_rn(y3);
                __half2 w0 = __halves2half2(h0, h1);
                __half2 w1 = __halves2half2(h2, h3);
                *(uint32_t*)(smc + OFF_YHI + o0) = *(uint32_t*)&w0;
                *(uint32_t*)(smc + OFF_YHI + o1) = *(uint32_t*)&w1;
                *(uint32_t*)(smc + OFF_P + o0) =
                    pack_f16(y0 - __half2float(h0), y1 - __half2float(h1));
                *(uint32_t*)(smc + OFF_P + o1) =
                    pack_f16(y2 - __half2float(h2), y3 - __half2float(h3));
            }
            {
                const int dv = nh * 8 + tg * 2;
                const int bb = rbase >> 6, ml = (rbase & 63) + g;
                float b0 = bv[h * DVD + dv], b1 = bv[h * DVD + dv + 1];
                float* v0 = sVf + (bb * 64 + ml) * 16 + dv;
                float* v1 = sVf + (bb * 64 + ml + 8) * 16 + dv;
                v0[0] = cV[mt][0] + b0;  v0[1] = cV[mt][1] + b1;
                v1[0] = cV[mt][2] + b0;  v1[1] = cV[mt][3] + b1;
            }
        }
        __syncthreads();                                   // ---- s2 ----

        // ======== prefetch next head's At/Wvt ========
        if (h + 1 < NH) {
            const char* gh = (const char*)g_Ahi[h + 1];
            const char* gl = (const char*)g_Alo[h + 1];
            #pragma unroll
            for (int j = 0; j < 8; j++) {
                uint32_t o = (uint32_t)(j * 4096 + tid * 16);
                CP_ASYNC16(sb + OFF_AHI + o, gh + o);
                CP_ASYNC16(sb + OFF_ALO + o, gl + o);
            }
            CP_ASYNC16(sb + OFF_WHI + tid * 16, (const char*)g_Whi[h + 1] + tid * 16);
            CP_ASYNC16(sb + OFF_WLO + tid * 16, (const char*)g_Wlo[h + 1] + tid * 16);
            CP_COMMIT();
        }

        // ======== GEMM2: C2[m,l] = X·Yᵀ (m16, all n of batch) ========
        float cS[8][4];
        #pragma unroll
        for (int n = 0; n < 8; n++)
            #pragma unroll
            for (int q = 0; q < 4; q++) cS[n][q] = 0.f;
        const uint32_t ybase = (uint32_t)(bb2 * 64 * 256);
        #pragma unroll
        for (int k = 0; k < 8; k++) {
            uint32_t ca = (uint32_t)(((2 * k + ahalf) ^ lr) << 4);
            uint32_t ahi[4], alo[4];
            ldsm_x4(ahi, sb + OFF_XHI + aRow2 + ca);
            ldsm_x4(alo, sb + OFF_XLO + aRow2 + ca);
            uint32_t cb = (uint32_t)(((2 * k + bhalf) ^ blr) << 4);
            uint32_t bo = ybase + bRowOff + cb;
            #pragma unroll
            for (int n = 0; n < 8; n++) {
                uint32_t o = bo + (uint32_t)(n * 2048);
                uint32_t bh[2], bl[2];
                ldsm_x2(bh, sb + OFF_YHI + o);
                ldsm_x2(bl, sb + OFF_P + o);
                mma_f32(cS[n], ahi, bh);
                {
                    uint32_t d0 = 0, d1 = 0;
                    mma_f16(d0, d1, ahi, bl);
                    mma_f16(d0, d1, alo, bh);
                    fold_corr(cS[n], d0, d1);
                }
            }
        }
        __syncthreads();                                   // ---- s3 ----

        // ======== bias + leaky + softmax over l, P -> smem ========
        {
            const int mbase = ((wid & 3) << 4) + g;
            #pragma unroll
            for (int pair = 0; pair < 2; pair++) {
                const int m = mbase + pair * 8;
                const float rm = srf[((bb2 << 6) + m) * 8 + h];
                float vals[16];
                float mx = -1e30f;
                #pragma unroll
                for (int n = 0; n < 8; n++) {
                    #pragma unroll
                    for (int j = 0; j < 2; j++) {
                        int l = n * 8 + tg * 2 + j;
                        float v = cS[n][pair * 2 + j]
                                + spf[((bb2 << 6) + l) * 8 + h] + rm;
                        v = v > 0.f ? v : 0.1f * v;
                        if (l >= LL) v = -1e30f;
                        vals[n * 2 + j] = v;
                        mx = fmaxf(mx, v);
                    }
                }
                mx = fmaxf(mx, __shfl_xor_sync(0xffffffffu, mx, 1));
                mx = fmaxf(mx, __shfl_xor_sync(0xffffffffu, mx, 2));
                float sum = 0.f;
                #pragma unroll
                for (int q = 0; q < 16; q++) {
                    float e = __expf(vals[q] - mx);
                    vals[q] = e;
                    sum += e;
                }
                sum += __shfl_xor_sync(0xffffffffu, sum, 1);
                sum += __shfl_xor_sync(0xffffffffu, sum, 2);
                float inv = 1.f / sum;
                float* prow = sPf + (bb2 * 64 + m) * 65;
                #pragma unroll
                for (int n = 0; n < 8; n++) {
                    prow[n * 8 + tg * 2]     = vals[n * 2] * inv;
                    prow[n * 8 + tg * 2 + 1] = vals[n * 2 + 1] * inv;
                }
            }
        }
        __syncthreads();                                   // ---- s4 ----

        // ======== out = relu(Pᵀ·V), store head slice ========
        #pragma unroll
        for (int it = 0; it < 2; it++) {
            int item = tid + it * NT;
            int b2 = item >> 8, l = (item >> 2) & 63, dv = (item & 3) * 4;
            if (l < LL) {
                float4 acc = make_float4(0.f, 0.f, 0.f, 0.f);
                const float* pcol = sPf + b2 * 64 * 65 + l;
                const float* vb   = sVf + b2 * 1024 + dv;
                #pragma unroll 10
                for (int m = 0; m < LL; m++) {
                    float p = pcol[m * 65];
                    float4 vv = *(const float4*)(vb + m * 16);
                    acc.x += p * vv.x;  acc.y += p * vv.y;
                    acc.z += p * vv.z;  acc.w += p * vv.w;
                }
                acc.x = fmaxf(acc.x, 0.f);  acc.y = fmaxf(acc.y, 0.f);
                acc.z = fmaxf(acc.z, 0.f);  acc.w = fmaxf(acc.w, 0.f);
                *(float4*)(out + (long long)(2 * bid + b2) * (LL * NH * DVD)
                               + l * (NH * DVD) + h * DVD + dv) = acc;
            }
        }
    }
}

// ---------------------------------------------------------------------------
extern "C" void kernel_launch(void* const* d_in, const int* in_sizes, int n_in,
                              void* d_out, int out_size) {
    const float* hid = (const float*)d_in[0];
    const float* Wq  = (const float*)d_in[1];
    const float* bq  = (const float*)d_in[2];
    const float* Wk  = (const float*)d_in[3];
    const float* bk  = (const float*)d_in[4];
    const float* Wv  = (const float*)d_in[5];
    const float* bv  = (const float*)d_in[6];
    float* out = (float*)d_out;

    const int nb = in_sizes[0] / (LL * FD);

    cudaFuncSetAttribute(attn_mma_kernel,
                         cudaFuncAttributeMaxDynamicSharedMemorySize, SMEM_TOTAL);

    precompute_kernel<<<dim3(NH, 8), 256>>>(Wq, bq, Wk, bk, Wv);
    attn_mma_kernel<<<nb / 2, NT, SMEM_TOTAL>>>(hid, bv, out);
}

// round 11
// speedup vs baseline: 1.3832x; 1.1089x over previous
#include <cuda_runtime.h>
#include <cuda_fp16.h>
#include <cstdint>

#define NH   8
#define FD   128
#define DVD  16
#define LL   50
#define NT   256

// ---------------- smem layout (bytes) ----------------
#define OFF_SP   0                      // p_all [2][64][8] f32 (+c folded)
#define OFF_SR   4096                   // r_all [2][64][8] f32
#define OFF_XHI  8192                   // X hi [128][256B] swizzled fp16
#define OFF_XLO  (OFF_XHI + 32768)
#define OFF_AHI  (OFF_XLO + 32768)      // At hi (per head, prefetched)
#define OFF_ALO  (OFF_AHI + 32768)      // At lo
#define OFF_WHI  (OFF_ALO + 32768)      // Wvt hi [16][256B]
#define OFF_WLO  (OFF_WHI + 4096)
#define OFF_YHI  (OFF_WLO + 4096)       // Y hi [128][256B] swizzled
#define OFF_V    (OFF_YHI + 32768)      // V f32 [2][64][16]
#define OFF_P    (OFF_V + 8192)         // Ylo (GEMM phase) / P f32 [2][64][65]
#define SMEM_TOTAL (OFF_P + 2*64*65*4)  // 221696

// ------------- precomputed folded weights (fp16 hi/lo) -------------
__device__ __align__(16) __half g_Ahi[NH][128 * 128];
__device__ __align__(16) __half g_Alo[NH][128 * 128];
__device__ __align__(16) __half g_Whi[NH][16 * 128];
__device__ __align__(16) __half g_Wlo[NH][16 * 128];
__device__ float g_u[NH][FD];
__device__ float g_w[NH][FD];
__device__ float g_c[NH];

// swizzled byte offset in a [rows][128 f16] tile (256B rows, 16B-chunk XOR)
__host__ __device__ __forceinline__ uint32_t xoff(int r, int c) {
    return (uint32_t)r * 256u
         + (uint32_t)(((((c >> 3) ^ (r & 7))) << 4) + (c & 7) * 2);
}

// ---------------- PTX helpers ----------------
__device__ __forceinline__ uint32_t smem_u32(const void* p) {
    uint32_t a;
    asm("{ .reg .u64 t; cvta.to.shared.u64 t, %1; cvt.u32.u64 %0, t; }"
        : "=r"(a) : "l"(p));
    return a;
}
__device__ __forceinline__ void ldsm_x4(uint32_t a[4], uint32_t addr) {
    asm volatile("ldmatrix.sync.aligned.m8n8.x4.shared.b16 {%0,%1,%2,%3}, [%4];"
                 : "=r"(a[0]), "=r"(a[1]), "=r"(a[2]), "=r"(a[3]) : "r"(addr));
}
__device__ __forceinline__ void ldsm_x2(uint32_t a[2], uint32_t addr) {
    asm volatile("ldmatrix.sync.aligned.m8n8.x2.shared.b16 {%0,%1}, [%2];"
                 : "=r"(a[0]), "=r"(a[1]) : "r"(addr));
}
// main term: f16 x f16 -> f32 accum
__device__ __forceinline__ void mma_f32(float c[4], const uint32_t a[4],
                                        const uint32_t b[2]) {
    asm volatile(
        "mma.sync.aligned.m16n8k16.row.col.f32.f16.f16.f32 "
        "{%0,%1,%2,%3}, {%4,%5,%6,%7}, {%8,%9}, {%0,%1,%2,%3};"
        : "+f"(c[0]), "+f"(c[1]), "+f"(c[2]), "+f"(c[3])
        : "r"(a[0]), "r"(a[1]), "r"(a[2]), "r"(a[3]), "r"(b[0]), "r"(b[1]));
}
// correction terms: f16 x f16 -> f16 accum (runs at 2x f32-accum rate)
__device__ __forceinline__ void mma_f16(uint32_t& d0, uint32_t& d1,
                                        const uint32_t a[4], const uint32_t b[2]) {
    asm volatile(
        "mma.sync.aligned.m16n8k16.row.col.f16.f16.f16.f16 "
        "{%0,%1}, {%2,%3,%4,%5}, {%6,%7}, {%0,%1};"
        : "+r"(d0), "+r"(d1)
        : "r"(a[0]), "r"(a[1]), "r"(a[2]), "r"(a[3]), "r"(b[0]), "r"(b[1]));
}
__device__ __forceinline__ void fold_corr(float c[4], uint32_t d0, uint32_t d1) {
    float2 f0 = __half22float2(*(__half2*)&d0);
    float2 f1 = __half22float2(*(__half2*)&d1);
    c[0] += f0.x;  c[1] += f0.y;  c[2] += f1.x;  c[3] += f1.y;
}
#define CP_ASYNC16(s, g) \
    asm volatile("cp.async.cg.shared.global [%0], [%1], 16;" :: "r"(s), "l"(g))
#define CP_COMMIT() asm volatile("cp.async.commit_group;" ::: "memory")
#define CP_WAIT0()  asm volatile("cp.async.wait_group 0;" ::: "memory")

__device__ __forceinline__ uint32_t pack_f16(float a, float b) {
    __half2 t = __floats2half2_rn(a, b);
    return *(uint32_t*)&t;
}

// ---------------------------------------------------------------------------
// Kernel 1: fold A = Wq Wk^T (fp16 hi/lo, swizzled At), Wvt hi/lo, biases
// ---------------------------------------------------------------------------
__global__ void precompute_kernel(const float* __restrict__ Wq,
                                  const float* __restrict__ bq,
                                  const float* __restrict__ Wk,
                                  const float* __restrict__ bk,
                                  const float* __restrict__ Wv) {
    const int h     = blockIdx.x;
    const int slice = blockIdx.y;
    const int tid   = threadIdx.x;
    const float* wq = Wq + h * FD * 128;
    const float* wk = Wk + h * FD * 128;

    #pragma unroll
    for (int r = 0; r < 8; r++) {
        int o  = slice * 2048 + r * 256 + tid;
        int f  = o >> 7;
        int fp = o & 127;
        const float* qrow = wq + f * 128;
        const float* krow = wk + fp * 128;
        float acc = 0.f;
        #pragma unroll 8
        for (int e = 0; e < 128; e++) acc += qrow[e] * krow[e];
        __half hi = __float2half_rn(acc);
        float rem = acc - __half2float(hi);
        uint32_t off = xoff(fp, f);
        *(__half*)((char*)g_Ahi[h] + off) = hi;
        *(__half*)((char*)g_Alo[h] + off) = __float2half_rn(rem);
    }
    if (slice == 0) {
        #pragma unroll
        for (int it = 0; it < 8; it++) {
            int idx = it * 256 + tid;
            int dv = idx >> 7, f = idx & 127;
            float v = Wv[h * FD * DVD + f * DVD + dv];
            __half hi = __float2half_rn(v);
            float rem = v - __half2float(hi);
            uint32_t off = xoff(dv, f);
            *(__half*)((char*)g_Whi[h] + off) = hi;
            *(__half*)((char*)g_Wlo[h] + off) = __float2half_rn(rem);
        }
        if (tid < FD) {
            float au = 0.f, aw = 0.f;
            #pragma unroll 8
            for (int e = 0; e < 128; e++) {
                au += wq[tid * 128 + e] * bk[h * 128 + e];
                aw += wk[tid * 128 + e] * bq[h * 128 + e];
            }
            g_u[h][tid] = au;
            g_w[h][tid] = aw;
        }
        if (tid == 128) {
            float c = 0.f;
            for (int e = 0; e < 128; e++) c += bq[h * 128 + e] * bk[h * 128 + e];
            g_c[h] = c;
        }
    }
}

// ---------------------------------------------------------------------------
// Kernel 2: HMMA attention, 256 threads, 2 batches per CTA (M = 128 rows).
// fp16 hi/lo; main f32-accum, corrections carried in f16 across k, folded once.
// GEMM1 runs in 2 passes of 4 n-tiles to bound register pressure.
// ---------------------------------------------------------------------------
__global__ void __launch_bounds__(NT, 1)
attn_mma_kernel(const float* __restrict__ hid,
                const float* __restrict__ bv,
                float* __restrict__ out) {
    extern __shared__ char smc[];
    const uint32_t sb = smem_u32(smc);
    const int tid  = threadIdx.x;
    const int wid  = tid >> 5;
    const int lane = tid & 31;
    const int bid  = blockIdx.x;

    float* spf = (float*)(smc + OFF_SP);   // [2][64][8]
    float* srf = (float*)(smc + OFF_SR);   // [2][64][8]
    float* sVf = (float*)(smc + OFF_V);
    float* sPf = (float*)(smc + OFF_P);

    // ---- load x (2 batches), fp16 hi/lo split, swizzled ----
    for (int i = tid; i < 128 * 64; i += NT) {
        int row = i >> 6;
        int cp  = (i & 63) * 2;
        int bb = row >> 6, l = row & 63;
        float v0 = 0.f, v1 = 0.f;
        if (l < LL) {
            const float* xr = hid + (long long)(2 * bid + bb) * (LL * FD) + l * FD + cp;
            v0 = xr[0]; v1 = xr[1];
        }
        __half h0 = __float2half_rn(v0), h1 = __float2half_rn(v1);
        float r0 = v0 - __half2float(h0), r1 = v1 - __half2float(h1);
        uint32_t off = xoff(row, cp);
        __half2 hw = __halves2half2(h0, h1);
        *(uint32_t*)(smc + OFF_XHI + off) = *(uint32_t*)&hw;
        *(uint32_t*)(smc + OFF_XLO + off) = pack_f16(r0, r1);
    }

    // ---- prologue: prefetch head 0 weights ----
    {
        const char* gh = (const char*)g_Ahi[0];
        const char* gl = (const char*)g_Alo[0];
        #pragma unroll
        for (int j = 0; j < 8; j++) {
            uint32_t o = (uint32_t)(j * 4096 + tid * 16);
            CP_ASYNC16(sb + OFF_AHI + o, gh + o);
            CP_ASYNC16(sb + OFF_ALO + o, gl + o);
        }
        CP_ASYNC16(sb + OFF_WHI + tid * 16, (const char*)g_Whi[0] + tid * 16);
        CP_ASYNC16(sb + OFF_WLO + tid * 16, (const char*)g_Wlo[0] + tid * 16);
        CP_COMMIT();
    }

    // ---- all-head p/r bias dots, once (overlaps prefetch) ----
    {
        int bb = tid >> 7;
        int l  = (tid >> 1) & 63;
        int pr = tid & 1;
        float acc[8];
        #pragma unroll
        for (int h2 = 0; h2 < 8; h2++) acc[h2] = 0.f;
        if (l < LL) {
            const float* xr = hid + (long long)(2 * bid + bb) * (LL * FD) + l * FD;
            const float* vb = pr ? &g_w[0][0] : &g_u[0][0];
            #pragma unroll 2
            for (int f = 0; f < FD; f += 4) {
                float4 xq = *(const float4*)(xr + f);
                #pragma unroll
                for (int h2 = 0; h2 < 8; h2++) {
                    const float* v = vb + h2 * FD + f;
                    acc[h2] += xq.x * v[0] + xq.y * v[1] + xq.z * v[2] + xq.w * v[3];
                }
            }
        }
        float* dst = pr ? srf : spf;
        #pragma unroll
        for (int h2 = 0; h2 < 8; h2++)
            dst[((bb << 6) + l) * 8 + h2] = acc[h2] + (pr ? 0.f : g_c[h2]);
    }

    // ---- ldmatrix lane-address components ----
    const int lr   = lane & 7;
    const int quad = lane >> 3;
    const int ahalf = quad >> 1;
    const int i15  = lane & 15;
    const int blr  = i15 & 7;
    const int bhalf = i15 >> 3;
    const uint32_t bRowOff = (uint32_t)blr * 256u;
    const int g  = lane >> 2;
    const int tg = lane & 3;

    // GEMM1: 4 m-slices (m32) x 2 n-halves; 2 passes of 4 n-tiles each
    const int ms = wid & 3;
    const int nh = wid >> 2;
    const uint32_t aRow1 = (uint32_t)(ms * 32 + lr + ((quad & 1) << 3)) * 256u;
    // GEMM2: m16 per warp, all n of batch bb2
    const uint32_t aRow2 = (uint32_t)(wid * 16 + lr + ((quad & 1) << 3)) * 256u;
    const int bb2 = wid >> 2;

    for (int h = 0; h < NH; h++) {
        CP_WAIT0();
        __syncthreads();                                   // ---- s1 ----

        // ======== GEMM1: Y = X·Atᵀ + V rider, 2 passes of 4 tiles ========
        #pragma unroll
        for (int pass = 0; pass < 2; pass++) {
            float cY[2][4][4];
            uint32_t cc[2][4][2];
            float cV[2][4];
            uint32_t cVc[2][2];
            #pragma unroll
            for (int mt = 0; mt < 2; mt++) {
                #pragma unroll
                for (int j = 0; j < 4; j++) {
                    #pragma unroll
                    for (int q = 0; q < 4; q++) cY[mt][j][q] = 0.f;
                    cc[mt][j][0] = 0u; cc[mt][j][1] = 0u;
                }
                #pragma unroll
                for (int q = 0; q < 4; q++) cV[mt][q] = 0.f;
                cVc[mt][0] = 0u; cVc[mt][1] = 0u;
            }

            #pragma unroll
            for (int k = 0; k < 8; k++) {
                uint32_t ca = (uint32_t)(((2 * k + ahalf) ^ lr) << 4);
                uint32_t ahi0[4], alo0[4], ahi1[4], alo1[4];
                ldsm_x4(ahi0, sb + OFF_XHI + aRow1 + ca);
                ldsm_x4(alo0, sb + OFF_XLO + aRow1 + ca);
                ldsm_x4(ahi1, sb + OFF_XHI + aRow1 + 4096u + ca);
                ldsm_x4(alo1, sb + OFF_XLO + aRow1 + 4096u + ca);
                uint32_t cb = (uint32_t)(((2 * k + bhalf) ^ blr) << 4);
                uint32_t bo = bRowOff + cb;
                #pragma unroll
                for (int j = 0; j < 4; j++) {
                    uint32_t o = bo + (uint32_t)((nh * 8 + pass * 4 + j) * 2048);
                    uint32_t bh[2], bl[2];
                    ldsm_x2(bh, sb + OFF_AHI + o);
                    ldsm_x2(bl, sb + OFF_ALO + o);
                    mma_f32(cY[0][j], ahi0, bh);
                    mma_f16(cc[0][j][0], cc[0][j][1], ahi0, bl);
                    mma_f16(cc[0][j][0], cc[0][j][1], alo0, bh);
                    mma_f32(cY[1][j], ahi1, bh);
                    mma_f16(cc[1][j][0], cc[1][j][1], ahi1, bl);
                    mma_f16(cc[1][j][0], cc[1][j][1], alo1, bh);
                }
                if (pass == 0) {
                    uint32_t o = bo + (uint32_t)(nh * 2048);
                    uint32_t bh[2], bl[2];
                    ldsm_x2(bh, sb + OFF_WHI + o);
                    ldsm_x2(bl, sb + OFF_WLO + o);
                    mma_f32(cV[0], ahi0, bh);
                    mma_f16(cVc[0][0], cVc[0][1], ahi0, bl);
                    mma_f16(cVc[0][0], cVc[0][1], alo0, bh);
                    mma_f32(cV[1], ahi1, bh);
                    mma_f16(cVc[1][0], cVc[1][1], ahi1, bl);
                    mma_f16(cVc[1][0], cVc[1][1], alo1, bh);
                }
            }

            // fold + write this pass's Y tiles (hi->YHI, lo->P) and V
            #pragma unroll
            for (int mt = 0; mt < 2; mt++) {
                const int rbase = ms * 32 + mt * 16;
                #pragma unroll
                for (int j = 0; j < 4; j++) {
                    fold_corr(cY[mt][j], cc[mt][j][0], cc[mt][j][1]);
                    int col = nh * 64 + (pass * 4 + j) * 8 + tg * 2;
                    uint32_t o0 = xoff(rbase + g, col);
                    uint32_t o1 = xoff(rbase + 8 + g, col);
                    float y0 = cY[mt][j][0], y1 = cY[mt][j][1];
                    float y2 = cY[mt][j][2], y3 = cY[mt][j][3];
                    __half h0 = __float2half_rn(y0), h1 = __float2half_rn(y1);
                    __half h2 = __float2half_rn(y2), h3 = __float2half_rn(y3);
                    __half2 w0 = __halves2half2(h0, h1);
                    __half2 w1 = __halves2half2(h2, h3);
                    *(uint32_t*)(smc + OFF_YHI + o0) = *(uint32_t*)&w0;
                    *(uint32_t*)(smc + OFF_YHI + o1) = *(uint32_t*)&w1;
                    *(uint32_t*)(smc + OFF_P + o0) =
                        pack_f16(y0 - __half2float(h0), y1 - __half2float(h1));
                    *(uint32_t*)(smc + OFF_P + o1) =
                        pack_f16(y2 - __half2float(h2), y3 - __half2float(h3));
                }
                if (pass == 0) {
                    fold_corr(cV[mt], cVc[mt][0], cVc[mt][1]);
                    const int dv = nh * 8 + tg * 2;
                    const int bb = rbase >> 6, ml = (rbase & 63) + g;
                    float b0 = bv[h * DVD + dv], b1 = bv[h * DVD + dv + 1];
                    float* v0 = sVf + (bb * 64 + ml) * 16 + dv;
                    float* v1 = sVf + (bb * 64 + ml + 8) * 16 + dv;
                    v0[0] = cV[mt][0] + b0;  v0[1] = cV[mt][1] + b1;
                    v1[0] = cV[mt][2] + b0;  v1[1] = cV[mt][3] + b1;
                }
            }
        }
        __syncthreads();                                   // ---- s2 ----

        // ======== prefetch next head's At/Wvt ========
        if (h + 1 < NH) {
            const char* gh = (const char*)g_Ahi[h + 1];
            const char* gl = (const char*)g_Alo[h + 1];
            #pragma unroll
            for (int j = 0; j < 8; j++) {
                uint32_t o = (uint32_t)(j * 4096 + tid * 16);
                CP_ASYNC16(sb + OFF_AHI + o, gh + o);
                CP_ASYNC16(sb + OFF_ALO + o, gl + o);
            }
            CP_ASYNC16(sb + OFF_WHI + tid * 16, (const char*)g_Whi[h + 1] + tid * 16);
            CP_ASYNC16(sb + OFF_WLO + tid * 16, (const char*)g_Wlo[h + 1] + tid * 16);
            CP_COMMIT();
        }

        // ======== GEMM2: C2[m,l] = X·Yᵀ (m16, all n; f16 corr carried) ====
        float cS[8][4];
        uint32_t cSc[8][2];
        #pragma unroll
        for (int n = 0; n < 8; n++) {
            #pragma unroll
            for (int q = 0; q < 4; q++) cS[n][q] = 0.f;
            cSc[n][0] = 0u; cSc[n][1] = 0u;
        }
        const uint32_t ybase = (uint32_t)(bb2 * 64 * 256);
        #pragma unroll
        for (int k = 0; k < 8; k++) {
            uint32_t ca = (uint32_t)(((2 * k + ahalf) ^ lr) << 4);
            uint32_t ahi[4], alo[4];
            ldsm_x4(ahi, sb + OFF_XHI + aRow2 + ca);
            ldsm_x4(alo, sb + OFF_XLO + aRow2 + ca);
            uint32_t cb = (uint32_t)(((2 * k + bhalf) ^ blr) << 4);
            uint32_t bo = ybase + bRowOff + cb;
            #pragma unroll
            for (int n = 0; n < 8; n++) {
                uint32_t o = bo + (uint32_t)(n * 2048);
                uint32_t bh[2], bl[2];
                ldsm_x2(bh, sb + OFF_YHI + o);
                ldsm_x2(bl, sb + OFF_P + o);
                mma_f32(cS[n], ahi, bh);
                mma_f16(cSc[n][0], cSc[n][1], ahi, bl);
                mma_f16(cSc[n][0], cSc[n][1], alo, bh);
            }
        }
        #pragma unroll
        for (int n = 0; n < 8; n++) fold_corr(cS[n], cSc[n][0], cSc[n][1]);
        __syncthreads();                                   // ---- s3 ----

        // ======== bias + leaky + softmax over l, P -> smem ========
        {
            const int mbase = ((wid & 3) << 4) + g;
            #pragma unroll
            for (int pair = 0; pair < 2; pair++) {
                const int m = mbase + pair * 8;
                const float rm = srf[((bb2 << 6) + m) * 8 + h];
                float vals[16];
                float mx = -1e30f;
                #pragma unroll
                for (int n = 0; n < 8; n++) {
                    #pragma unroll
                    for (int j = 0; j < 2; j++) {
                        int l = n * 8 + tg * 2 + j;
                        float v = cS[n][pair * 2 + j]
                                + spf[((bb2 << 6) + l) * 8 + h] + rm;
                        v = v > 0.f ? v : 0.1f * v;
                        if (l >= LL) v = -1e30f;
                        vals[n * 2 + j] = v;
                        mx = fmaxf(mx, v);
                    }
                }
                mx = fmaxf(mx, __shfl_xor_sync(0xffffffffu, mx, 1));
                mx = fmaxf(mx, __shfl_xor_sync(0xffffffffu, mx, 2));
                float sum = 0.f;
                #pragma unroll
                for (int q = 0; q < 16; q++) {
                    float e = __expf(vals[q] - mx);
                    vals[q] = e;
                    sum += e;
                }
                sum += __shfl_xor_sync(0xffffffffu, sum, 1);
                sum += __shfl_xor_sync(0xffffffffu, sum, 2);
                float inv = 1.f / sum;
                float* prow = sPf + (bb2 * 64 + m) * 65;
                #pragma unroll
                for (int n = 0; n < 8; n++) {
                    prow[n * 8 + tg * 2]     = vals[n * 2] * inv;
                    prow[n * 8 + tg * 2 + 1] = vals[n * 2 + 1] * inv;
                }
            }
        }
        __syncthreads();                                   // ---- s4 ----

        // ======== out = relu(Pᵀ·V), store head slice ========
        #pragma unroll
        for (int it = 0; it < 2; it++) {
            int item = tid + it * NT;
            int b2 = item >> 8, l = (item >> 2) & 63, dv = (item & 3) * 4;
            if (l < LL) {
                float4 acc = make_float4(0.f, 0.f, 0.f, 0.f);
                const float* pcol = sPf + b2 * 64 * 65 + l;
                const float* vb   = sVf + b2 * 1024 + dv;
                #pragma unroll 10
                for (int m = 0; m < LL; m++) {
                    float p = pcol[m * 65];
                    float4 vv = *(const float4*)(vb + m * 16);
                    acc.x += p * vv.x;  acc.y += p * vv.y;
                    acc.z += p * vv.z;  acc.w += p * vv.w;
                }
                acc.x = fmaxf(acc.x, 0.f);  acc.y = fmaxf(acc.y, 0.f);
                acc.z = fmaxf(acc.z, 0.f);  acc.w = fmaxf(acc.w, 0.f);
                *(float4*)(out + (long long)(2 * bid + b2) * (LL * NH * DVD)
                               + l * (NH * DVD) + h * DVD + dv) = acc;
            }
        }
    }
}

// ---------------------------------------------------------------------------
extern "C" void kernel_launch(void* const* d_in, const int* in_sizes, int n_in,
                              void* d_out, int out_size) {
    const float* hid = (const float*)d_in[0];
    const float* Wq  = (const float*)d_in[1];
    const float* bq  = (const float*)d_in[2];
    const float* Wk  = (const float*)d_in[3];
    const float* bk  = (const float*)d_in[4];
    const float* Wv  = (const float*)d_in[5];
    const float* bv  = (const float*)d_in[6];
    float* out = (float*)d_out;

    const int nb = in_sizes[0] / (LL * FD);

    cudaFuncSetAttribute(attn_mma_kernel,
                         cudaFuncAttributeMaxDynamicSharedMemorySize, SMEM_TOTAL);

    precompute_kernel<<<dim3(NH, 8), 256>>>(Wq, bq, Wk, bk, Wv);
    attn_mma_kernel<<<nb / 2, NT, SMEM_TOTAL>>>(hid, bv, out);
}

// round 12
// speedup vs baseline: 1.3990x; 1.0114x over previous
#include <cuda_runtime.h>
#include <cuda_fp16.h>
#include <cstdint>

#define NH   8
#define FD   128
#define DVD  16
#define LL   50
#define NT   256

// ---------------- smem layout (bytes) ----------------
#define OFF_SP   0                      // p_all [2][64][8] f32 (+c folded)
#define OFF_SR   4096                   // r_all [2][64][8] f32
#define OFF_XHI  8192                   // X hi [128][256B] swizzled fp16
#define OFF_XLO  (OFF_XHI + 32768)
#define OFF_AHI  (OFF_XLO + 32768)      // At hi (per head, prefetched)
#define OFF_ALO  (OFF_AHI + 32768)      // At lo
#define OFF_WHI  (OFF_ALO + 32768)      // Wvt hi [16][256B]
#define OFF_WLO  (OFF_WHI + 4096)
#define OFF_YHI  (OFF_WLO + 4096)       // Y hi [128][256B] swizzled
#define OFF_V    (OFF_YHI + 32768)      // V f32 [2][64][16]
#define OFF_P    (OFF_V + 8192)         // Ylo (GEMM phase) / P f32 [2][64][65]
#define SMEM_TOTAL (OFF_P + 2*64*65*4)  // 221696

// ------------- precomputed folded weights (fp16 hi/lo) -------------
__device__ __align__(16) __half g_Ahi[NH][128 * 128];
__device__ __align__(16) __half g_Alo[NH][128 * 128];
__device__ __align__(16) __half g_Whi[NH][16 * 128];
__device__ __align__(16) __half g_Wlo[NH][16 * 128];
__device__ float g_u[NH][FD];
__device__ float g_w[NH][FD];
__device__ float g_c[NH];

// swizzled byte offset in a [rows][128 f16] tile (256B rows, 16B-chunk XOR)
__host__ __device__ __forceinline__ uint32_t xoff(int r, int c) {
    return (uint32_t)r * 256u
         + (uint32_t)(((((c >> 3) ^ (r & 7))) << 4) + (c & 7) * 2);
}

// ---------------- PTX helpers ----------------
__device__ __forceinline__ uint32_t smem_u32(const void* p) {
    uint32_t a;
    asm("{ .reg .u64 t; cvta.to.shared.u64 t, %1; cvt.u32.u64 %0, t; }"
        : "=r"(a) : "l"(p));
    return a;
}
__device__ __forceinline__ void ldsm_x4(uint32_t a[4], uint32_t addr) {
    asm volatile("ldmatrix.sync.aligned.m8n8.x4.shared.b16 {%0,%1,%2,%3}, [%4];"
                 : "=r"(a[0]), "=r"(a[1]), "=r"(a[2]), "=r"(a[3]) : "r"(addr));
}
__device__ __forceinline__ void ldsm_x2(uint32_t a[2], uint32_t addr) {
    asm volatile("ldmatrix.sync.aligned.m8n8.x2.shared.b16 {%0,%1}, [%2];"
                 : "=r"(a[0]), "=r"(a[1]) : "r"(addr));
}
// main term: f16 x f16 -> f32 accum
__device__ __forceinline__ void mma_f32(float c[4], const uint32_t a[4],
                                        const uint32_t b0, const uint32_t b1) {
    asm volatile(
        "mma.sync.aligned.m16n8k16.row.col.f32.f16.f16.f32 "
        "{%0,%1,%2,%3}, {%4,%5,%6,%7}, {%8,%9}, {%0,%1,%2,%3};"
        : "+f"(c[0]), "+f"(c[1]), "+f"(c[2]), "+f"(c[3])
        : "r"(a[0]), "r"(a[1]), "r"(a[2]), "r"(a[3]), "r"(b0), "r"(b1));
}
// correction terms: f16 x f16 -> f16 accum (2x f32-accum rate)
__device__ __forceinline__ void mma_f16(uint32_t& d0, uint32_t& d1,
                                        const uint32_t a[4],
                                        const uint32_t b0, const uint32_t b1) {
    asm volatile(
        "mma.sync.aligned.m16n8k16.row.col.f16.f16.f16.f16 "
        "{%0,%1}, {%2,%3,%4,%5}, {%6,%7}, {%0,%1};"
        : "+r"(d0), "+r"(d1)
        : "r"(a[0]), "r"(a[1]), "r"(a[2]), "r"(a[3]), "r"(b0), "r"(b1));
}
__device__ __forceinline__ void fold_corr(float c[4], uint32_t d0, uint32_t d1) {
    float2 f0 = __half22float2(*(__half2*)&d0);
    float2 f1 = __half22float2(*(__half2*)&d1);
    c[0] += f0.x;  c[1] += f0.y;  c[2] += f1.x;  c[3] += f1.y;
}
#define CP_ASYNC16(s, g) \
    asm volatile("cp.async.cg.shared.global [%0], [%1], 16;" :: "r"(s), "l"(g))
#define CP_COMMIT() asm volatile("cp.async.commit_group;" ::: "memory")
#define CP_WAIT0()  asm volatile("cp.async.wait_group 0;" ::: "memory")

__device__ __forceinline__ uint32_t pack_f16(float a, float b) {
    __half2 t = __floats2half2_rn(a, b);
    return *(uint32_t*)&t;
}

// ---------------------------------------------------------------------------
// Kernel 1: fold A = Wq Wk^T (fp16 hi/lo, swizzled At), Wvt hi/lo, biases
// ---------------------------------------------------------------------------
__global__ void precompute_kernel(const float* __restrict__ Wq,
                                  const float* __restrict__ bq,
                                  const float* __restrict__ Wk,
                                  const float* __restrict__ bk,
                                  const float* __restrict__ Wv) {
    const int h     = blockIdx.x;
    const int slice = blockIdx.y;
    const int tid   = threadIdx.x;
    const float* wq = Wq + h * FD * 128;
    const float* wk = Wk + h * FD * 128;

    #pragma unroll
    for (int r = 0; r < 8; r++) {
        int o  = slice * 2048 + r * 256 + tid;
        int f  = o >> 7;
        int fp = o & 127;
        const float* qrow = wq + f * 128;
        const float* krow = wk + fp * 128;
        float acc = 0.f;
        #pragma unroll 8
        for (int e = 0; e < 128; e++) acc += qrow[e] * krow[e];
        __half hi = __float2half_rn(acc);
        float rem = acc - __half2float(hi);
        uint32_t off = xoff(fp, f);
        *(__half*)((char*)g_Ahi[h] + off) = hi;
        *(__half*)((char*)g_Alo[h] + off) = __float2half_rn(rem);
    }
    if (slice == 0) {
        #pragma unroll
        for (int it = 0; it < 8; it++) {
            int idx = it * 256 + tid;
            int dv = idx >> 7, f = idx & 127;
            float v = Wv[h * FD * DVD + f * DVD + dv];
            __half hi = __float2half_rn(v);
            float rem = v - __half2float(hi);
            uint32_t off = xoff(dv, f);
            *(__half*)((char*)g_Whi[h] + off) = hi;
            *(__half*)((char*)g_Wlo[h] + off) = __float2half_rn(rem);
        }
        if (tid < FD) {
            float au = 0.f, aw = 0.f;
            #pragma unroll 8
            for (int e = 0; e < 128; e++) {
                au += wq[tid * 128 + e] * bk[h * 128 + e];
                aw += wk[tid * 128 + e] * bq[h * 128 + e];
            }
            g_u[h][tid] = au;
            g_w[h][tid] = aw;
        }
        if (tid == 128) {
            float c = 0.f;
            for (int e = 0; e < 128; e++) c += bq[h * 128 + e] * bk[h * 128 + e];
            g_c[h] = c;
        }
    }
}

// ---------------------------------------------------------------------------
// Kernel 2: HMMA attention, 256 threads, 2 batches per CTA (M = 128 rows).
// fp16 hi/lo; main f32-accum + deferred f16-accum corrections.
// B-operands loaded pairwise via ldmatrix.x4; GEMM2 skips fully-masked tile 7.
// ---------------------------------------------------------------------------
__global__ void __launch_bounds__(NT, 1)
attn_mma_kernel(const float* __restrict__ hid,
                const float* __restrict__ bv,
                float* __restrict__ out) {
    extern __shared__ char smc[];
    const uint32_t sb = smem_u32(smc);
    const int tid  = threadIdx.x;
    const int wid  = tid >> 5;
    const int lane = tid & 31;
    const int bid  = blockIdx.x;

    float* spf = (float*)(smc + OFF_SP);   // [2][64][8]
    float* srf = (float*)(smc + OFF_SR);   // [2][64][8]
    float* sVf = (float*)(smc + OFF_V);
    float* sPf = (float*)(smc + OFF_P);

    // ---- load x (2 batches), fp16 hi/lo split, swizzled ----
    for (int i = tid; i < 128 * 64; i += NT) {
        int row = i >> 6;
        int cp  = (i & 63) * 2;
        int bb = row >> 6, l = row & 63;
        float v0 = 0.f, v1 = 0.f;
        if (l < LL) {
            const float* xr = hid + (long long)(2 * bid + bb) * (LL * FD) + l * FD + cp;
            v0 = xr[0]; v1 = xr[1];
        }
        __half h0 = __float2half_rn(v0), h1 = __float2half_rn(v1);
        float r0 = v0 - __half2float(h0), r1 = v1 - __half2float(h1);
        uint32_t off = xoff(row, cp);
        __half2 hw = __halves2half2(h0, h1);
        *(uint32_t*)(smc + OFF_XHI + off) = *(uint32_t*)&hw;
        *(uint32_t*)(smc + OFF_XLO + off) = pack_f16(r0, r1);
    }

    // ---- prologue: prefetch head 0 weights ----
    {
        const char* gh = (const char*)g_Ahi[0];
        const char* gl = (const char*)g_Alo[0];
        #pragma unroll
        for (int j = 0; j < 8; j++) {
            uint32_t o = (uint32_t)(j * 4096 + tid * 16);
            CP_ASYNC16(sb + OFF_AHI + o, gh + o);
            CP_ASYNC16(sb + OFF_ALO + o, gl + o);
        }
        CP_ASYNC16(sb + OFF_WHI + tid * 16, (const char*)g_Whi[0] + tid * 16);
        CP_ASYNC16(sb + OFF_WLO + tid * 16, (const char*)g_Wlo[0] + tid * 16);
        CP_COMMIT();
    }

    // ---- all-head p/r bias dots, once (overlaps prefetch) ----
    {
        int bb = tid >> 7;
        int l  = (tid >> 1) & 63;
        int pr = tid & 1;
        float acc[8];
        #pragma unroll
        for (int h2 = 0; h2 < 8; h2++) acc[h2] = 0.f;
        if (l < LL) {
            const float* xr = hid + (long long)(2 * bid + bb) * (LL * FD) + l * FD;
            const float* vb = pr ? &g_w[0][0] : &g_u[0][0];
            #pragma unroll 2
            for (int f = 0; f < FD; f += 4) {
                float4 xq = *(const float4*)(xr + f);
                #pragma unroll
                for (int h2 = 0; h2 < 8; h2++) {
                    const float* v = vb + h2 * FD + f;
                    acc[h2] += xq.x * v[0] + xq.y * v[1] + xq.z * v[2] + xq.w * v[3];
                }
            }
        }
        float* dst = pr ? srf : spf;
        #pragma unroll
        for (int h2 = 0; h2 < 8; h2++)
            dst[((bb << 6) + l) * 8 + h2] = acc[h2] + (pr ? 0.f : g_c[h2]);
    }

    // ---- ldmatrix lane-address components ----
    const int lr   = lane & 7;
    const int quad = lane >> 3;
    const int ahalf = quad >> 1;
    const int i15  = lane & 15;
    const int blr  = i15 & 7;
    const int bhalf = i15 >> 3;
    const uint32_t bRowOff = (uint32_t)blr * 256u;
    const uint32_t bPair   = (uint32_t)((lane >> 4) << 11);  // +2048B for 2nd tile
    const int g  = lane >> 2;
    const int tg = lane & 3;

    // GEMM1: 4 m-slices (m32) x 2 n-halves; 2 passes of 4 n-tiles each
    const int ms = wid & 3;
    const int nh = wid >> 2;
    const uint32_t aRow1 = (uint32_t)(ms * 32 + lr + ((quad & 1) << 3)) * 256u;
    // GEMM2: m16 per warp, all n of batch bb2
    const uint32_t aRow2 = (uint32_t)(wid * 16 + lr + ((quad & 1) << 3)) * 256u;
    const int bb2 = wid >> 2;

    for (int h = 0; h < NH; h++) {
        CP_WAIT0();
        __syncthreads();                                   // ---- s1 ----

        // ======== GEMM1: Y = X·Atᵀ + V rider, 2 passes of 4 tiles ========
        #pragma unroll
        for (int pass = 0; pass < 2; pass++) {
            float cY[2][4][4];
            uint32_t cc[2][4][2];
            float cV[2][4];
            uint32_t cVc[2][2];
            #pragma unroll
            for (int mt = 0; mt < 2; mt++) {
                #pragma unroll
                for (int j = 0; j < 4; j++) {
                    #pragma unroll
                    for (int q = 0; q < 4; q++) cY[mt][j][q] = 0.f;
                    cc[mt][j][0] = 0u; cc[mt][j][1] = 0u;
                }
                #pragma unroll
                for (int q = 0; q < 4; q++) cV[mt][q] = 0.f;
                cVc[mt][0] = 0u; cVc[mt][1] = 0u;
            }

            #pragma unroll
            for (int k = 0; k < 8; k++) {
                uint32_t ca = (uint32_t)(((2 * k + ahalf) ^ lr) << 4);
                uint32_t ahi0[4], alo0[4], ahi1[4], alo1[4];
                ldsm_x4(ahi0, sb + OFF_XHI + aRow1 + ca);
                ldsm_x4(alo0, sb + OFF_XLO + aRow1 + ca);
                ldsm_x4(ahi1, sb + OFF_XHI + aRow1 + 4096u + ca);
                ldsm_x4(alo1, sb + OFF_XLO + aRow1 + 4096u + ca);
                uint32_t cb = (uint32_t)(((2 * k + bhalf) ^ blr) << 4);
                uint32_t bo = bRowOff + cb + bPair;
                #pragma unroll
                for (int jp = 0; jp < 2; jp++) {   // tile pair (2 n-tiles per x4)
                    uint32_t o = bo + (uint32_t)((nh * 8 + pass * 4 + jp * 2) * 2048);
                    uint32_t bh[4], bl[4];
                    ldsm_x4(bh, sb + OFF_AHI + o);
                    ldsm_x4(bl, sb + OFF_ALO + o);
                    const int j0 = jp * 2, j1 = jp * 2 + 1;
                    mma_f32(cY[0][j0], ahi0, bh[0], bh[1]);
                    mma_f16(cc[0][j0][0], cc[0][j0][1], ahi0, bl[0], bl[1]);
                    mma_f16(cc[0][j0][0], cc[0][j0][1], alo0, bh[0], bh[1]);
                    mma_f32(cY[1][j0], ahi1, bh[0], bh[1]);
                    mma_f16(cc[1][j0][0], cc[1][j0][1], ahi1, bl[0], bl[1]);
                    mma_f16(cc[1][j0][0], cc[1][j0][1], alo1, bh[0], bh[1]);
                    mma_f32(cY[0][j1], ahi0, bh[2], bh[3]);
                    mma_f16(cc[0][j1][0], cc[0][j1][1], ahi0, bl[2], bl[3]);
                    mma_f16(cc[0][j1][0], cc[0][j1][1], alo0, bh[2], bh[3]);
                    mma_f32(cY[1][j1], ahi1, bh[2], bh[3]);
                    mma_f16(cc[1][j1][0], cc[1][j1][1], ahi1, bl[2], bl[3]);
                    mma_f16(cc[1][j1][0], cc[1][j1][1], alo1, bh[2], bh[3]);
                }
                if (pass == 0) {
                    uint32_t o = bRowOff + cb + (uint32_t)(nh * 2048);
                    uint32_t bh[2], bl[2];
                    ldsm_x2(bh, sb + OFF_WHI + o);
                    ldsm_x2(bl, sb + OFF_WLO + o);
                    mma_f32(cV[0], ahi0, bh[0], bh[1]);
                    mma_f16(cVc[0][0], cVc[0][1], ahi0, bl[0], bl[1]);
                    mma_f16(cVc[0][0], cVc[0][1], alo0, bh[0], bh[1]);
                    mma_f32(cV[1], ahi1, bh[0], bh[1]);
                    mma_f16(cVc[1][0], cVc[1][1], ahi1, bl[0], bl[1]);
                    mma_f16(cVc[1][0], cVc[1][1], alo1, bh[0], bh[1]);
                }
            }

            // fold + write this pass's Y tiles (hi->YHI, lo->P) and V
            #pragma unroll
            for (int mt = 0; mt < 2; mt++) {
                const int rbase = ms * 32 + mt * 16;
                #pragma unroll
                for (int j = 0; j < 4; j++) {
                    fold_corr(cY[mt][j], cc[mt][j][0], cc[mt][j][1]);
                    int col = nh * 64 + (pass * 4 + j) * 8 + tg * 2;
                    uint32_t o0 = xoff(rbase + g, col);
                    uint32_t o1 = xoff(rbase + 8 + g, col);
                    float y0 = cY[mt][j][0], y1 = cY[mt][j][1];
                    float y2 = cY[mt][j][2], y3 = cY[mt][j][3];
                    __half h0 = __float2half_rn(y0), h1 = __float2half_rn(y1);
                    __half h2 = __float2half_rn(y2), h3 = __float2half_rn(y3);
                    __half2 w0 = __halves2half2(h0, h1);
                    __half2 w1 = __halves2half2(h2, h3);
                    *(uint32_t*)(smc + OFF_YHI + o0) = *(uint32_t*)&w0;
                    *(uint32_t*)(smc + OFF_YHI + o1) = *(uint32_t*)&w1;
                    *(uint32_t*)(smc + OFF_P + o0) =
                        pack_f16(y0 - __half2float(h0), y1 - __half2float(h1));
                    *(uint32_t*)(smc + OFF_P + o1) =
                        pack_f16(y2 - __half2float(h2), y3 - __half2float(h3));
                }
                if (pass == 0) {
                    fold_corr(cV[mt], cVc[mt][0], cVc[mt][1]);
                    const int dv = nh * 8 + tg * 2;
                    const int bb = rbase >> 6, ml = (rbase & 63) + g;
                    float b0 = bv[h * DVD + dv], b1 = bv[h * DVD + dv + 1];
                    float* v0 = sVf + (bb * 64 + ml) * 16 + dv;
                    float* v1 = sVf + (bb * 64 + ml + 8) * 16 + dv;
                    v0[0] = cV[mt][0] + b0;  v0[1] = cV[mt][1] + b1;
                    v1[0] = cV[mt][2] + b0;  v1[1] = cV[mt][3] + b1;
                }
            }
        }
        __syncthreads();                                   // ---- s2 ----

        // ======== prefetch next head's At/Wvt ========
        if (h + 1 < NH) {
            const char* gh = (const char*)g_Ahi[h + 1];
            const char* gl = (const char*)g_Alo[h + 1];
            #pragma unroll
            for (int j = 0; j < 8; j++) {
                uint32_t o = (uint32_t)(j * 4096 + tid * 16);
                CP_ASYNC16(sb + OFF_AHI + o, gh + o);
                CP_ASYNC16(sb + OFF_ALO + o, gl + o);
            }
            CP_ASYNC16(sb + OFF_WHI + tid * 16, (const char*)g_Whi[h + 1] + tid * 16);
            CP_ASYNC16(sb + OFF_WLO + tid * 16, (const char*)g_Wlo[h + 1] + tid * 16);
            CP_COMMIT();
        }

        // ======== GEMM2: C2[m,l] = X·Yᵀ, 7 n-tiles (tile 7 fully masked) ====
        float cS[7][4];
        uint32_t cSc[7][2];
        #pragma unroll
        for (int n = 0; n < 7; n++) {
            #pragma unroll
            for (int q = 0; q < 4; q++) cS[n][q] = 0.f;
            cSc[n][0] = 0u; cSc[n][1] = 0u;
        }
        const uint32_t ybase = (uint32_t)(bb2 * 64 * 256);
        #pragma unroll
        for (int k = 0; k < 8; k++) {
            uint32_t ca = (uint32_t)(((2 * k + ahalf) ^ lr) << 4);
            uint32_t ahi[4], alo[4];
            ldsm_x4(ahi, sb + OFF_XHI + aRow2 + ca);
            ldsm_x4(alo, sb + OFF_XLO + aRow2 + ca);
            uint32_t cb = (uint32_t)(((2 * k + bhalf) ^ blr) << 4);
            uint32_t bo = ybase + bRowOff + cb;
            #pragma unroll
            for (int np = 0; np < 3; np++) {   // tile pairs (0,1)(2,3)(4,5)
                uint32_t o = bo + bPair + (uint32_t)(np * 2 * 2048);
                uint32_t bh[4], bl[4];
                ldsm_x4(bh, sb + OFF_YHI + o);
                ldsm_x4(bl, sb + OFF_P + o);
                const int n0 = np * 2, n1 = np * 2 + 1;
                mma_f32(cS[n0], ahi, bh[0], bh[1]);
                mma_f16(cSc[n0][0], cSc[n0][1], ahi, bl[0], bl[1]);
                mma_f16(cSc[n0][0], cSc[n0][1], alo, bh[0], bh[1]);
                mma_f32(cS[n1], ahi, bh[2], bh[3]);
                mma_f16(cSc[n1][0], cSc[n1][1], ahi, bl[2], bl[3]);
                mma_f16(cSc[n1][0], cSc[n1][1], alo, bh[2], bh[3]);
            }
            {   // tile 6 alone
                uint32_t o = bo + (uint32_t)(6 * 2048);
                uint32_t bh[2], bl[2];
                ldsm_x2(bh, sb + OFF_YHI + o);
                ldsm_x2(bl, sb + OFF_P + o);
                mma_f32(cS[6], ahi, bh[0], bh[1]);
                mma_f16(cSc[6][0], cSc[6][1], ahi, bl[0], bl[1]);
                mma_f16(cSc[6][0], cSc[6][1], alo, bh[0], bh[1]);
            }
        }
        #pragma unroll
        for (int n = 0; n < 7; n++) fold_corr(cS[n], cSc[n][0], cSc[n][1]);
        __syncthreads();                                   // ---- s3 ----

        // ======== bias + leaky + softmax over l, P -> smem ========
        {
            const int mbase = ((wid & 3) << 4) + g;
            #pragma unroll
            for (int pair = 0; pair < 2; pair++) {
                const int m = mbase + pair * 8;
                const float rm = srf[((bb2 << 6) + m) * 8 + h];
                float vals[14];
                float mx = -1e30f;
                #pragma unroll
                for (int n = 0; n < 7; n++) {
                    #pragma unroll
                    for (int j = 0; j < 2; j++) {
                        int l = n * 8 + tg * 2 + j;
                        float v = cS[n][pair * 2 + j]
                                + spf[((bb2 << 6) + l) * 8 + h] + rm;
                        v = v > 0.f ? v : 0.1f * v;
                        if (l >= LL) v = -1e30f;
                        vals[n * 2 + j] = v;
                        mx = fmaxf(mx, v);
                    }
                }
                mx = fmaxf(mx, __shfl_xor_sync(0xffffffffu, mx, 1));
                mx = fmaxf(mx, __shfl_xor_sync(0xffffffffu, mx, 2));
                float sum = 0.f;
                #pragma unroll
                for (int q = 0; q < 14; q++) {
                    float e = __expf(vals[q] - mx);
                    vals[q] = e;
                    sum += e;
                }
                sum += __shfl_xor_sync(0xffffffffu, sum, 1);
                sum += __shfl_xor_sync(0xffffffffu, sum, 2);
                float inv = 1.f / sum;
                float* prow = sPf + (bb2 * 64 + m) * 65;
                #pragma unroll
                for (int n = 0; n < 7; n++) {
                    prow[n * 8 + tg * 2]     = vals[n * 2] * inv;
                    prow[n * 8 + tg * 2 + 1] = vals[n * 2 + 1] * inv;
                }
            }
        }
        __syncthreads();                                   // ---- s4 ----

        // ======== out = relu(Pᵀ·V), store head slice ========
        #pragma unroll
        for (int it = 0; it < 2; it++) {
            int item = tid + it * NT;
            int b2 = item >> 8, l = (item >> 2) & 63, dv = (item & 3) * 4;
            if (l < LL) {
                float4 acc = make_float4(0.f, 0.f, 0.f, 0.f);
                const float* pcol = sPf + b2 * 64 * 65 + l;
                const float* vb   = sVf + b2 * 1024 + dv;
                #pragma unroll 10
                for (int m = 0; m < LL; m++) {
                    float p = pcol[m * 65];
                    float4 vv = *(const float4*)(vb + m * 16);
                    acc.x += p * vv.x;  acc.y += p * vv.y;
                    acc.z += p * vv.z;  acc.w += p * vv.w;
                }
                acc.x = fmaxf(acc.x, 0.f);  acc.y = fmaxf(acc.y, 0.f);
                acc.z = fmaxf(acc.z, 0.f);  acc.w = fmaxf(acc.w, 0.f);
                *(float4*)(out + (long long)(2 * bid + b2) * (LL * NH * DVD)
                               + l * (NH * DVD) + h * DVD + dv) = acc;
            }
        }
    }
}

// ---------------------------------------------------------------------------
extern "C" void kernel_launch(void* const* d_in, const int* in_sizes, int n_in,
                              void* d_out, int out_size) {
    const float* hid = (const float*)d_in[0];
    const float* Wq  = (const float*)d_in[1];
    const float* bq  = (const float*)d_in[2];
    const float* Wk  = (const float*)d_in[3];
    const float* bk  = (const float*)d_in[4];
    const float* Wv  = (const float*)d_in[5];
    const float* bv  = (const float*)d_in[6];
    float* out = (float*)d_out;

    const int nb = in_sizes[0] / (LL * FD);

    cudaFuncSetAttribute(attn_mma_kernel,
                         cudaFuncAttributeMaxDynamicSharedMemorySize, SMEM_TOTAL);

    precompute_kernel<<<dim3(NH, 8), 256>>>(Wq, bq, Wk, bk, Wv);
    attn_mma_kernel<<<nb / 2, NT, SMEM_TOTAL>>>(hid, bv, out);
}